// round 1
// baseline (speedup 1.0000x reference)
#include <cuda_runtime.h>
#include <cuda_bf16.h>
#include <math.h>

// Problem constants
#define BATCH 2
#define SEQ 2048
#define DMODEL 512
#define KDIM 256      // total key dim (8 heads x 32)
#define VDIM 256
#define ODIM 512
#define NHEADS 8
#define HDIM 32       // per-head dim

// Scratch (static device globals; no allocation allowed)
__device__ float g_q[BATCH * SEQ * KDIM];    // 4 MB
__device__ float g_k[BATCH * SEQ * KDIM];    // 4 MB
__device__ float g_v[BATCH * SEQ * VDIM];    // 4 MB
__device__ float g_ctx[BATCH * SEQ * VDIM];  // 4 MB

// ----------------------------------------------------------------------------
// Tiled SGEMM with bias: C[M,N] = A[M,K] @ W[K,N] + bias[N]
// Block tile 64x64, K-tile 16, 256 threads, 4x4 per thread, float4 smem reads.
// ----------------------------------------------------------------------------
__global__ __launch_bounds__(256) void gemm_bias_kernel(
    const float* __restrict__ A, const float* __restrict__ W,
    const float* __restrict__ bias, float* __restrict__ C,
    int M, int N, int K)
{
    __shared__ float As[16][64];   // A transposed: As[k][m]
    __shared__ float Ws[16][64];   // Ws[k][n]

    const int tid = threadIdx.x;
    const int tx = tid & 15;       // 0..15  -> 4 columns each
    const int ty = tid >> 4;       // 0..15  -> 4 rows each
    const int m0 = blockIdx.y * 64;
    const int n0 = blockIdx.x * 64;

    float4 acc[4];
    acc[0] = make_float4(0.f, 0.f, 0.f, 0.f);
    acc[1] = acc[0]; acc[2] = acc[0]; acc[3] = acc[0];

    const int lrow = tid >> 2;     // 0..63
    const int lk4  = tid & 3;      // 0..3
    const int wk   = tid >> 4;     // 0..15
    const int wn4  = tid & 15;     // 0..15

    for (int k0 = 0; k0 < K; k0 += 16) {
        // Load A tile (64 rows x 16 k), transpose into As[k][m]
        float4 av = *(const float4*)(A + (size_t)(m0 + lrow) * K + k0 + lk4 * 4);
        As[lk4 * 4 + 0][lrow] = av.x;
        As[lk4 * 4 + 1][lrow] = av.y;
        As[lk4 * 4 + 2][lrow] = av.z;
        As[lk4 * 4 + 3][lrow] = av.w;
        // Load W tile (16 k x 64 n)
        *(float4*)&Ws[wk][wn4 * 4] =
            *(const float4*)(W + (size_t)(k0 + wk) * N + n0 + wn4 * 4);
        __syncthreads();

        #pragma unroll
        for (int kk = 0; kk < 16; kk++) {
            float4 a = *(float4*)&As[kk][ty * 4];
            float4 w = *(float4*)&Ws[kk][tx * 4];
            acc[0].x += a.x * w.x; acc[0].y += a.x * w.y; acc[0].z += a.x * w.z; acc[0].w += a.x * w.w;
            acc[1].x += a.y * w.x; acc[1].y += a.y * w.y; acc[1].z += a.y * w.z; acc[1].w += a.y * w.w;
            acc[2].x += a.z * w.x; acc[2].y += a.z * w.y; acc[2].z += a.z * w.z; acc[2].w += a.z * w.w;
            acc[3].x += a.w * w.x; acc[3].y += a.w * w.y; acc[3].z += a.w * w.z; acc[3].w += a.w * w.w;
        }
        __syncthreads();
    }

    float4 bv = *(const float4*)(bias + n0 + tx * 4);
    #pragma unroll
    for (int i = 0; i < 4; i++) {
        int row = m0 + ty * 4 + i;
        float4 o;
        o.x = acc[i].x + bv.x; o.y = acc[i].y + bv.y;
        o.z = acc[i].z + bv.z; o.w = acc[i].w + bv.w;
        *(float4*)(C + (size_t)row * N + n0 + tx * 4) = o;
    }
}

// ----------------------------------------------------------------------------
// Flash-style attention.
// Grid: (SEQ/128, NHEADS, BATCH); 128 threads; each thread owns 1 query row.
// Per key-tile (32 keys): stage K/V tile + mask tile in smem (coalesced),
// compute scores, online softmax, accumulate context (dv=32 in registers).
// ----------------------------------------------------------------------------
#define QT 128
#define KT 32

__global__ __launch_bounds__(128) void attn_kernel(
    const float* __restrict__ gq, const float* __restrict__ gk,
    const float* __restrict__ gv, const float* __restrict__ mask,
    float* __restrict__ gctx)
{
    __shared__ float ks[KT][HDIM];
    __shared__ float vs[KT][HDIM];
    __shared__ float sc[QT][KT + 1];   // mask tile, then scores (stride 33: conflict-free)

    const int qt  = blockIdx.x;
    const int h   = blockIdx.y;
    const int b   = blockIdx.z;
    const int tid = threadIdx.x;
    const int row = qt * QT + tid;     // query index within sequence

    const float scale = 1.0f / 16.0f;  // 1/sqrt(KDIM=256)

    // Query row in registers, pre-scaled
    float4 q4[8];
    {
        const float4* qp = (const float4*)(gq + ((size_t)(b * SEQ + row)) * KDIM + h * HDIM);
        #pragma unroll
        for (int i = 0; i < 8; i++) {
            float4 t = qp[i];
            t.x *= scale; t.y *= scale; t.z *= scale; t.w *= scale;
            q4[i] = t;
        }
    }

    float4 acc[8];
    #pragma unroll
    for (int i = 0; i < 8; i++) acc[i] = make_float4(0.f, 0.f, 0.f, 0.f);
    float m = -INFINITY, l = 0.f;

    const float* maskb = mask + (size_t)b * SEQ * SEQ;

    for (int k0 = 0; k0 < SEQ; k0 += KT) {
        __syncthreads();   // protect smem reuse from previous iteration

        // K/V tiles: 32 rows x 32 dims = 256 float4s, 128 threads -> 2 each
        #pragma unroll
        for (int it = 0; it < 2; it++) {
            int i = tid + it * 128;
            int r = i >> 3;            // 0..31 key row
            int c = i & 7;             // 0..7 float4 within row
            size_t src = ((size_t)(b * SEQ + k0 + r)) * KDIM + h * HDIM;
            ((float4*)ks[r])[c] = ((const float4*)(gk + src))[c];
            ((float4*)vs[r])[c] = ((const float4*)(gv + src))[c];
        }
        // Mask tile: 128 rows x 32 keys, coalesced
        #pragma unroll
        for (int it = 0; it < 32; it++) {
            int i = tid + it * 128;
            int r = i >> 5;            // 0..127
            int c = i & 31;            // 0..31
            sc[r][c] = maskb[(size_t)(qt * QT + r) * SEQ + k0 + c];
        }
        __syncthreads();

        // Scores for my row; overwrite mask in smem with the score
        float mt = -INFINITY;
        #pragma unroll 4
        for (int j = 0; j < KT; j++) {
            float s = 0.f;
            #pragma unroll
            for (int i = 0; i < 8; i++) {
                float4 kk = ((float4*)ks[j])[i];
                s += q4[i].x * kk.x + q4[i].y * kk.y + q4[i].z * kk.z + q4[i].w * kk.w;
            }
            s += sc[tid][j];
            sc[tid][j] = s;
            mt = fmaxf(mt, s);
        }

        // Online softmax rescale
        float mnew = fmaxf(m, mt);
        float corr = (m == -INFINITY) ? 0.f : __expf(m - mnew);
        l *= corr;
        #pragma unroll
        for (int i = 0; i < 8; i++) {
            acc[i].x *= corr; acc[i].y *= corr; acc[i].z *= corr; acc[i].w *= corr;
        }

        // Accumulate p * V
        #pragma unroll 4
        for (int j = 0; j < KT; j++) {
            float p = __expf(sc[tid][j] - mnew);
            l += p;
            #pragma unroll
            for (int i = 0; i < 8; i++) {
                float4 vv = ((float4*)vs[j])[i];
                acc[i].x += p * vv.x; acc[i].y += p * vv.y;
                acc[i].z += p * vv.z; acc[i].w += p * vv.w;
            }
        }
        m = mnew;
    }

    // Normalize and write context (merged-head layout [B*S, 256])
    float inv = 1.f / l;
    float4* op = (float4*)(gctx + ((size_t)(b * SEQ + row)) * VDIM + h * HDIM);
    #pragma unroll
    for (int i = 0; i < 8; i++) {
        float4 o = acc[i];
        o.x *= inv; o.y *= inv; o.z *= inv; o.w *= inv;
        op[i] = o;
    }
}

// ----------------------------------------------------------------------------
// Launch
// Input order (metadata): V, Q, K, mask, Wq, bq, Wk, bk, Wv, bv, Wo, bo
// ----------------------------------------------------------------------------
extern "C" void kernel_launch(void* const* d_in, const int* in_sizes, int n_in,
                              void* d_out, int out_size)
{
    const float* V    = (const float*)d_in[0];
    const float* Q    = (const float*)d_in[1];
    const float* K    = (const float*)d_in[2];
    const float* mask = (const float*)d_in[3];
    const float* Wq   = (const float*)d_in[4];
    const float* bq   = (const float*)d_in[5];
    const float* Wk   = (const float*)d_in[6];
    const float* bk   = (const float*)d_in[7];
    const float* Wv   = (const float*)d_in[8];
    const float* bv   = (const float*)d_in[9];
    const float* Wo   = (const float*)d_in[10];
    const float* bo   = (const float*)d_in[11];
    float* out = (float*)d_out;

    float *dq, *dk, *dv, *dctx;
    cudaGetSymbolAddress((void**)&dq,   g_q);
    cudaGetSymbolAddress((void**)&dk,   g_k);
    cudaGetSymbolAddress((void**)&dv,   g_v);
    cudaGetSymbolAddress((void**)&dctx, g_ctx);

    const int M = BATCH * SEQ;   // 4096

    // QKV projections (three GEMMs, M=4096, K=512, N=256)
    dim3 gridP(KDIM / 64, M / 64);
    gemm_bias_kernel<<<gridP, 256>>>(Q, Wq, bq, dq, M, KDIM, DMODEL);
    gemm_bias_kernel<<<gridP, 256>>>(K, Wk, bk, dk, M, KDIM, DMODEL);
    gemm_bias_kernel<<<gridP, 256>>>(V, Wv, bv, dv, M, VDIM, DMODEL);

    // Flash attention
    dim3 gridA(SEQ / QT, NHEADS, BATCH);
    attn_kernel<<<gridA, 128>>>(dq, dk, dv, mask, dctx);

    // Output projection (M=4096, K=256, N=512)
    dim3 gridO(ODIM / 64, M / 64);
    gemm_bias_kernel<<<gridO, 256>>>(dctx, Wo, bo, out, M, ODIM, VDIM);
}

// round 5
// speedup vs baseline: 2.0762x; 2.0762x over previous
#include <cuda_runtime.h>
#include <cstdint>

// ---------------- problem constants ----------------
#define BATCH 2
#define SEQ 2048
#define DMODEL 512
#define KDIM 256
#define VDIM 256
#define ODIM 512
#define NHEADS 8
#define HDIM 32
#define LOG2E 1.4426950408889634f

// scratch
__device__ float g_q[BATCH * SEQ * KDIM];
__device__ float g_k[BATCH * SEQ * KDIM];
__device__ float g_v[BATCH * SEQ * VDIM];
__device__ float g_ctx[BATCH * SEQ * VDIM];

// ---------------- helpers ----------------
__device__ __forceinline__ float tf32r(float x) {
    float y; asm("cvt.rna.tf32.f32 %0, %1;" : "=f"(y) : "f"(x)); return y;
}
__device__ __forceinline__ float ex2f(float x) {
    float y; asm("ex2.approx.ftz.f32 %0, %1;" : "=f"(y) : "f"(x)); return y;
}
// m16n8k8 tf32 mma: D += A*B, row.col
__device__ __forceinline__ void mma8(float* c, const uint32_t* a, uint32_t b0, uint32_t b1) {
    asm volatile(
        "mma.sync.aligned.m16n8k8.row.col.f32.tf32.tf32.f32 "
        "{%0,%1,%2,%3}, {%4,%5,%6,%7}, {%8,%9}, {%0,%1,%2,%3};"
        : "+f"(c[0]), "+f"(c[1]), "+f"(c[2]), "+f"(c[3])
        : "r"(a[0]), "r"(a[1]), "r"(a[2]), "r"(a[3]), "r"(b0), "r"(b1));
}

// ============================================================================
// tf32 GEMM + bias: C[M,N] = A[M,K] @ W[K,N] + bias
// BM=128, BN=64, BK=32; 256 threads = 8 warps in 4(m) x 2(n); warp tile 32x32.
// ============================================================================
__global__ __launch_bounds__(256) void gemm_tf32(
    const float* __restrict__ A, const float* __restrict__ W,
    const float* __restrict__ bias, float* __restrict__ C,
    int M, int N, int K)
{
    __shared__ float As[32][132];   // As[k][m], padded stride
    __shared__ float Bs[32][68];    // Bs[k][n]

    const int tid = threadIdx.x;
    const int w = tid >> 5, lane = tid & 31;
    const int g = lane >> 2, t = lane & 3;
    const int wm = w >> 1, wn = w & 1;
    const int m0 = blockIdx.y * 128, n0 = blockIdx.x * 64;

    float acc[2][4][4];
    #pragma unroll
    for (int i = 0; i < 2; i++)
        #pragma unroll
        for (int j = 0; j < 4; j++)
            #pragma unroll
            for (int q = 0; q < 4; q++) acc[i][j][q] = 0.f;

    for (int k0 = 0; k0 < K; k0 += 32) {
        // stage A tile (128 x 32), transposed, tf32-rounded
        #pragma unroll
        for (int i = 0; i < 4; i++) {
            int idx = tid + i * 256;
            int r = idx >> 3, c = idx & 7;
            float4 v = *(const float4*)(A + (size_t)(m0 + r) * K + k0 + c * 4);
            As[c * 4 + 0][r] = tf32r(v.x);
            As[c * 4 + 1][r] = tf32r(v.y);
            As[c * 4 + 2][r] = tf32r(v.z);
            As[c * 4 + 3][r] = tf32r(v.w);
        }
        // stage B tile (32 x 64)
        #pragma unroll
        for (int i = 0; i < 2; i++) {
            int idx = tid + i * 256;
            int r = idx >> 4, c = idx & 15;
            float4 v = *(const float4*)(W + (size_t)(k0 + r) * N + n0 + c * 4);
            Bs[r][c * 4 + 0] = tf32r(v.x);
            Bs[r][c * 4 + 1] = tf32r(v.y);
            Bs[r][c * 4 + 2] = tf32r(v.z);
            Bs[r][c * 4 + 3] = tf32r(v.w);
        }
        __syncthreads();

        #pragma unroll
        for (int kt = 0; kt < 4; kt++) {
            uint32_t af[2][4];
            #pragma unroll
            for (int mt = 0; mt < 2; mt++) {
                int mb = wm * 32 + mt * 16 + g;
                af[mt][0] = __float_as_uint(As[kt * 8 + t][mb]);
                af[mt][1] = __float_as_uint(As[kt * 8 + t][mb + 8]);
                af[mt][2] = __float_as_uint(As[kt * 8 + t + 4][mb]);
                af[mt][3] = __float_as_uint(As[kt * 8 + t + 4][mb + 8]);
            }
            #pragma unroll
            for (int nt = 0; nt < 4; nt++) {
                int nb = wn * 32 + nt * 8 + g;
                uint32_t b0 = __float_as_uint(Bs[kt * 8 + t][nb]);
                uint32_t b1 = __float_as_uint(Bs[kt * 8 + t + 4][nb]);
                mma8(acc[0][nt], af[0], b0, b1);
                mma8(acc[1][nt], af[1], b0, b1);
            }
        }
        __syncthreads();
    }

    #pragma unroll
    for (int nt = 0; nt < 4; nt++) {
        int col = n0 + wn * 32 + nt * 8 + 2 * t;
        float2 bv = *(const float2*)(bias + col);
        #pragma unroll
        for (int mt = 0; mt < 2; mt++) {
            int row = m0 + wm * 32 + mt * 16 + g;
            float2 o0 = make_float2(acc[mt][nt][0] + bv.x, acc[mt][nt][1] + bv.y);
            float2 o1 = make_float2(acc[mt][nt][2] + bv.x, acc[mt][nt][3] + bv.y);
            *(float2*)(C + (size_t)row * N + col) = o0;
            *(float2*)(C + (size_t)(row + 8) * N + col) = o1;
        }
    }
}

// ============================================================================
// Flash attention via mma.sync tf32.
// CTA: 128 q-rows x (head, batch); 8 warps; warp owns 16 q-rows end-to-end.
// Key tiles of 64; no online max (scores bounded); P repacked C-frag -> A-frag
// via shuffles; ctx accumulated in fp32 C-frags.
// ============================================================================
#define QS_STR 132
#define KS_STR 68
#define VS_STR 36
#define OFF_K  (32 * QS_STR)                 // 4224
#define KBUF   (32 * KS_STR)                 // 2176
#define OFF_V  (OFF_K + 2 * KBUF)            // 8576
#define VBUF   (64 * VS_STR)                 // 2304
#define SM_FLOATS (OFF_V + 2 * VBUF)         // 13184 floats = 52736 B

__global__ __launch_bounds__(256, 2) void attn_mma(
    const float* __restrict__ gq, const float* __restrict__ gk,
    const float* __restrict__ gv, const float* __restrict__ mask,
    float* __restrict__ gctx)
{
    extern __shared__ float sm[];
    float* Qs = sm;
    float* Ks = sm + OFF_K;
    float* Vs = sm + OFF_V;

    const int tid = threadIdx.x;
    const int w = tid >> 5, lane = tid & 31;
    const int g = lane >> 2, t = lane & 3;
    const int h = blockIdx.x, qt = blockIdx.y, b = blockIdx.z;

    const float* qsrc = gq + ((size_t)(b * SEQ + qt * 128)) * KDIM + h * HDIM;
    const float* ksrc = gk + ((size_t)(b * SEQ)) * KDIM + h * HDIM;
    const float* vsrc = gv + ((size_t)(b * SEQ)) * KDIM + h * HDIM;

    // stage Q (pre-scaled by log2e/sqrt(256)), transposed [dk][q]
    const float qscale = LOG2E / 16.0f;
    #pragma unroll
    for (int i = 0; i < 4; i++) {
        int idx = tid + i * 256;
        int r = idx >> 3, c = idx & 7;
        float4 v = *(const float4*)(qsrc + (size_t)r * KDIM + c * 4);
        Qs[(c * 4 + 0) * QS_STR + r] = tf32r(v.x * qscale);
        Qs[(c * 4 + 1) * QS_STR + r] = tf32r(v.y * qscale);
        Qs[(c * 4 + 2) * QS_STR + r] = tf32r(v.z * qscale);
        Qs[(c * 4 + 3) * QS_STR + r] = tf32r(v.w * qscale);
    }
    // stage K0 [dk][key], V0 [key][dv]
    #pragma unroll
    for (int i = 0; i < 2; i++) {
        int idx = tid + i * 256;
        int r = idx >> 3, c = idx & 7;
        float4 kv = *(const float4*)(ksrc + (size_t)r * KDIM + c * 4);
        Ks[(c * 4 + 0) * KS_STR + r] = tf32r(kv.x);
        Ks[(c * 4 + 1) * KS_STR + r] = tf32r(kv.y);
        Ks[(c * 4 + 2) * KS_STR + r] = tf32r(kv.z);
        Ks[(c * 4 + 3) * KS_STR + r] = tf32r(kv.w);
        float4 vv = *(const float4*)(vsrc + (size_t)r * KDIM + c * 4);
        *(float4*)(Vs + r * VS_STR + c * 4) =
            make_float4(tf32r(vv.x), tf32r(vv.y), tf32r(vv.z), tf32r(vv.w));
    }
    __syncthreads();

    // Q fragments: 4 k-tiles x 4 regs (held for whole kernel)
    uint32_t qf[4][4];
    #pragma unroll
    for (int kt = 0; kt < 4; kt++) {
        int mb = w * 16 + g;
        qf[kt][0] = __float_as_uint(Qs[(kt * 8 + t) * QS_STR + mb]);
        qf[kt][1] = __float_as_uint(Qs[(kt * 8 + t) * QS_STR + mb + 8]);
        qf[kt][2] = __float_as_uint(Qs[(kt * 8 + t + 4) * QS_STR + mb]);
        qf[kt][3] = __float_as_uint(Qs[(kt * 8 + t + 4) * QS_STR + mb + 8]);
    }

    const float* mr0 = mask + (size_t)b * SEQ * SEQ
                     + (size_t)(qt * 128 + w * 16 + g) * SEQ + 2 * t;
    const float* mr1 = mr0 + (size_t)8 * SEQ;

    float ctx[4][4];
    #pragma unroll
    for (int i = 0; i < 4; i++)
        #pragma unroll
        for (int j = 0; j < 4; j++) ctx[i][j] = 0.f;
    float lg = 0.f, lh = 0.f;

    const int srcA = (lane & ~3) | (t >> 1);
    const int srcB = srcA + 2;

    for (int kt0 = 0; kt0 < 32; kt0++) {
        float* ks = Ks + (kt0 & 1) * KBUF;
        float* vs = Vs + (kt0 & 1) * VBUF;

        // prefetch next K/V tile into registers
        float4 pk[2], pv[2];
        if (kt0 < 31) {
            const float* kn = ksrc + (size_t)(kt0 + 1) * 64 * KDIM;
            const float* vn = vsrc + (size_t)(kt0 + 1) * 64 * KDIM;
            #pragma unroll
            for (int i = 0; i < 2; i++) {
                int idx = tid + i * 256;
                int r = idx >> 3, c = idx & 7;
                pk[i] = *(const float4*)(kn + (size_t)r * KDIM + c * 4);
                pv[i] = *(const float4*)(vn + (size_t)r * KDIM + c * 4);
            }
        }
        // prefetch mask fragments for this tile
        float2 m0v[8], m1v[8];
        #pragma unroll
        for (int nt = 0; nt < 8; nt++) {
            m0v[nt] = *(const float2*)(mr0 + kt0 * 64 + nt * 8);
            m1v[nt] = *(const float2*)(mr1 + kt0 * 64 + nt * 8);
        }

        // S = Q @ K^T  (16 rows x 64 keys per warp)
        float sc[8][4];
        #pragma unroll
        for (int nt = 0; nt < 8; nt++)
            #pragma unroll
            for (int i = 0; i < 4; i++) sc[nt][i] = 0.f;
        #pragma unroll
        for (int kt = 0; kt < 4; kt++) {
            #pragma unroll
            for (int nt = 0; nt < 8; nt++) {
                int nb = nt * 8 + g;
                uint32_t b0 = __float_as_uint(ks[(kt * 8 + t) * KS_STR + nb]);
                uint32_t b1 = __float_as_uint(ks[(kt * 8 + t + 4) * KS_STR + nb]);
                mma8(sc[nt], qf[kt], b0, b1);
            }
        }

        // epilogue: p = exp2(s + mask*log2e); accumulate row sums; tf32-round p
        #pragma unroll
        for (int nt = 0; nt < 8; nt++) {
            float p0 = ex2f(__fmaf_rn(m0v[nt].x, LOG2E, sc[nt][0]));
            float p1 = ex2f(__fmaf_rn(m0v[nt].y, LOG2E, sc[nt][1]));
            float p2 = ex2f(__fmaf_rn(m1v[nt].x, LOG2E, sc[nt][2]));
            float p3 = ex2f(__fmaf_rn(m1v[nt].y, LOG2E, sc[nt][3]));
            lg += p0 + p1;
            lh += p2 + p3;
            sc[nt][0] = tf32r(p0); sc[nt][1] = tf32r(p1);
            sc[nt][2] = tf32r(p2); sc[nt][3] = tf32r(p3);
        }

        // ctx += P @ V : repack P C-frags -> A-frags via shuffles
        #pragma unroll
        for (int kt2 = 0; kt2 < 8; kt2++) {
            uint32_t a[4];
            float x0, x1;
            x0 = __shfl_sync(0xFFFFFFFFu, sc[kt2][0], srcA);
            x1 = __shfl_sync(0xFFFFFFFFu, sc[kt2][1], srcA);
            a[0] = __float_as_uint((t & 1) ? x1 : x0);
            x0 = __shfl_sync(0xFFFFFFFFu, sc[kt2][2], srcA);
            x1 = __shfl_sync(0xFFFFFFFFu, sc[kt2][3], srcA);
            a[1] = __float_as_uint((t & 1) ? x1 : x0);
            x0 = __shfl_sync(0xFFFFFFFFu, sc[kt2][0], srcB);
            x1 = __shfl_sync(0xFFFFFFFFu, sc[kt2][1], srcB);
            a[2] = __float_as_uint((t & 1) ? x1 : x0);
            x0 = __shfl_sync(0xFFFFFFFFu, sc[kt2][2], srcB);
            x1 = __shfl_sync(0xFFFFFFFFu, sc[kt2][3], srcB);
            a[3] = __float_as_uint((t & 1) ? x1 : x0);
            #pragma unroll
            for (int nt2 = 0; nt2 < 4; nt2++) {
                int nb = nt2 * 8 + g;
                uint32_t b0 = __float_as_uint(vs[(kt2 * 8 + t) * VS_STR + nb]);
                uint32_t b1 = __float_as_uint(vs[(kt2 * 8 + t + 4) * VS_STR + nb]);
                mma8(ctx[nt2], a, b0, b1);
            }
        }

        // commit prefetched tile to the other buffer
        if (kt0 < 31) {
            float* kd = Ks + ((kt0 + 1) & 1) * KBUF;
            float* vd = Vs + ((kt0 + 1) & 1) * VBUF;
            #pragma unroll
            for (int i = 0; i < 2; i++) {
                int idx = tid + i * 256;
                int r = idx >> 3, c = idx & 7;
                kd[(c * 4 + 0) * KS_STR + r] = tf32r(pk[i].x);
                kd[(c * 4 + 1) * KS_STR + r] = tf32r(pk[i].y);
                kd[(c * 4 + 2) * KS_STR + r] = tf32r(pk[i].z);
                kd[(c * 4 + 3) * KS_STR + r] = tf32r(pk[i].w);
                *(float4*)(vd + r * VS_STR + c * 4) =
                    make_float4(tf32r(pv[i].x), tf32r(pv[i].y), tf32r(pv[i].z), tf32r(pv[i].w));
            }
        }
        __syncthreads();
    }

    // row-sum reduction over the 4 lanes of each group
    lg += __shfl_xor_sync(0xFFFFFFFFu, lg, 1);
    lg += __shfl_xor_sync(0xFFFFFFFFu, lg, 2);
    lh += __shfl_xor_sync(0xFFFFFFFFu, lh, 1);
    lh += __shfl_xor_sync(0xFFFFFFFFu, lh, 2);
    float ig = 1.0f / lg, ih = 1.0f / lh;

    size_t rbase = ((size_t)(b * SEQ + qt * 128 + w * 16 + g)) * VDIM + h * HDIM;
    #pragma unroll
    for (int nt2 = 0; nt2 < 4; nt2++) {
        int col = nt2 * 8 + 2 * t;
        *(float2*)(gctx + rbase + col) =
            make_float2(ctx[nt2][0] * ig, ctx[nt2][1] * ig);
        *(float2*)(gctx + rbase + (size_t)8 * VDIM + col) =
            make_float2(ctx[nt2][2] * ih, ctx[nt2][3] * ih);
    }
}

// ---------------- launch ----------------
extern "C" void kernel_launch(void* const* d_in, const int* in_sizes, int n_in,
                              void* d_out, int out_size)
{
    const float* V    = (const float*)d_in[0];
    const float* Q    = (const float*)d_in[1];
    const float* K    = (const float*)d_in[2];
    const float* mask = (const float*)d_in[3];
    const float* Wq   = (const float*)d_in[4];
    const float* bq   = (const float*)d_in[5];
    const float* Wk   = (const float*)d_in[6];
    const float* bk   = (const float*)d_in[7];
    const float* Wv   = (const float*)d_in[8];
    const float* bv   = (const float*)d_in[9];
    const float* Wo   = (const float*)d_in[10];
    const float* bo   = (const float*)d_in[11];
    float* out = (float*)d_out;

    float *dq, *dk, *dv, *dctx;
    cudaGetSymbolAddress((void**)&dq,   g_q);
    cudaGetSymbolAddress((void**)&dk,   g_k);
    cudaGetSymbolAddress((void**)&dv,   g_v);
    cudaGetSymbolAddress((void**)&dctx, g_ctx);

    const int M = BATCH * SEQ;   // 4096

    // QKV projections: M=4096, N=256, K=512
    dim3 gridP(KDIM / 64, M / 128);
    gemm_tf32<<<gridP, 256>>>(Q, Wq, bq, dq, M, KDIM, DMODEL);
    gemm_tf32<<<gridP, 256>>>(K, Wk, bk, dk, M, KDIM, DMODEL);
    gemm_tf32<<<gridP, 256>>>(V, Wv, bv, dv, M, VDIM, DMODEL);

    // attention
    cudaFuncSetAttribute(attn_mma, cudaFuncAttributeMaxDynamicSharedMemorySize,
                         SM_FLOATS * sizeof(float));
    dim3 gridA(NHEADS, SEQ / 128, BATCH);
    attn_mma<<<gridA, 256, SM_FLOATS * sizeof(float)>>>(dq, dk, dv, mask, dctx);

    // output projection: M=4096, N=512, K=256
    dim3 gridO(ODIM / 64, M / 128);
    gemm_tf32<<<gridO, 256>>>(dctx, Wo, bo, out, M, ODIM, VDIM);
}

// round 6
// speedup vs baseline: 3.0540x; 1.4710x over previous
#include <cuda_runtime.h>
#include <cstdint>

// ---------------- problem constants ----------------
#define BATCH 2
#define SEQ 2048
#define DMODEL 512
#define KDIM 256
#define VDIM 256
#define ODIM 512
#define NHEADS 8
#define HDIM 32
#define LOG2E 1.4426950408889634f
#define MTOT (BATCH * SEQ)          // 4096

// scratch
__device__ float g_q[MTOT * KDIM];
__device__ float g_k[MTOT * KDIM];
__device__ float g_vt[KDIM * MTOT];    // V projection, transposed: [n=256][m=4096]
__device__ float g_ctx[MTOT * VDIM];

// ---------------- helpers ----------------
__device__ __forceinline__ uint32_t smem_u32(const void* p) {
    uint32_t a;
    asm("{ .reg .u64 t; cvta.to.shared.u64 t, %1; cvt.u32.u64 %0, t; }" : "=r"(a) : "l"(p));
    return a;
}
__device__ __forceinline__ float tf32r(float x) {
    float y; asm("cvt.rna.tf32.f32 %0, %1;" : "=f"(y) : "f"(x)); return y;
}
__device__ __forceinline__ float ex2f(float x) {
    float y; asm("ex2.approx.ftz.f32 %0, %1;" : "=f"(y) : "f"(x)); return y;
}
__device__ __forceinline__ void mma8(float* c, const uint32_t* a, uint32_t b0, uint32_t b1) {
    asm volatile(
        "mma.sync.aligned.m16n8k8.row.col.f32.tf32.tf32.f32 "
        "{%0,%1,%2,%3}, {%4,%5,%6,%7}, {%8,%9}, {%0,%1,%2,%3};"
        : "+f"(c[0]), "+f"(c[1]), "+f"(c[2]), "+f"(c[3])
        : "r"(a[0]), "r"(a[1]), "r"(a[2]), "r"(a[3]), "r"(b0), "r"(b1));
}
__device__ __forceinline__ void ldsm4(uint32_t* r, uint32_t a) {
    asm volatile("ldmatrix.sync.aligned.m8n8.x4.shared.b16 {%0,%1,%2,%3}, [%4];"
        : "=r"(r[0]), "=r"(r[1]), "=r"(r[2]), "=r"(r[3]) : "r"(a));
}
#define CP16(dst, src) \
    asm volatile("cp.async.ca.shared.global [%0], [%1], 16;" :: "r"(dst), "l"(src))
#define CPCOMMIT() asm volatile("cp.async.commit_group;" ::: "memory")
#define CPWAIT0()  asm volatile("cp.async.wait_group 0;" ::: "memory")

// swizzled byte offset within a tile of row-bytes RB (row < 8k aligned blocks)
#define SWZ(row, col) ((uint32_t)(col) ^ ((uint32_t)((row) & 7) << 4))

// ============================================================================
// tf32 GEMM + bias, ldmatrix + register double buffering.
// BM=128, BN=64, BK=32; 8 warps 4(m)x2(n); warp tile 32x32.
// As natural [m][k] (128B rows, swizzled); Bs transposed [n][k] (128B rows).
// MODE 0: C[m][n] = tf32r((acc+bias)*oscale)     (Q/K projections)
// MODE 1: Ct[n][M] = tf32r((acc+bias)*oscale)    (V projection, transposed out)
// MODE 2: C[m][n] = acc+bias                      (output projection)
// ============================================================================
template<int MODE>
__global__ __launch_bounds__(256) void gemm_tc(
    const float* __restrict__ A, const float* __restrict__ W,
    const float* __restrict__ bias, float* __restrict__ C,
    int M, int N, int K, float oscale)
{
    __shared__ char smg[49152];
    const uint32_t sb = smem_u32(smg);

    const int tid = threadIdx.x;
    const int w = tid >> 5, lane = tid & 31;
    const int g = lane >> 2, t = lane & 3;
    const int wm = w >> 1, wn = w & 1;
    const int m0 = blockIdx.y * 128, n0 = blockIdx.x * 64;

    float acc[2][4][4];
    #pragma unroll
    for (int i = 0; i < 2; i++)
        #pragma unroll
        for (int j = 0; j < 4; j++)
            #pragma unroll
            for (int q = 0; q < 4; q++) acc[i][j][q] = 0.f;

    const int nkb = K >> 5;

    // stage block 0
    {
        #pragma unroll
        for (int i = 0; i < 4; i++) {
            int idx = tid + i * 256;
            int r = idx >> 3, c = idx & 7;
            float4 v = *(const float4*)(A + (size_t)(m0 + r) * K + c * 4);
            v.x = tf32r(v.x); v.y = tf32r(v.y); v.z = tf32r(v.z); v.w = tf32r(v.w);
            *(float4*)(smg + r * 128 + SWZ(r, c * 16)) = v;
        }
        #pragma unroll
        for (int i = 0; i < 2; i++) {
            int idx = tid + i * 256;
            int k = idx & 31, c = idx >> 5;
            float4 v = *(const float4*)(W + (size_t)k * N + n0 + c * 4);
            float vv[4] = { tf32r(v.x), tf32r(v.y), tf32r(v.z), tf32r(v.w) };
            #pragma unroll
            for (int j = 0; j < 4; j++) {
                int n = c * 4 + j;
                *(float*)(smg + 32768 + n * 128 + SWZ(n, k * 4)) = vv[j];
            }
        }
    }
    __syncthreads();

    for (int kb = 0; kb < nkb; kb++) {
        const int cur = kb & 1;
        float4 pa[4], pw[2];
        if (kb + 1 < nkb) {
            #pragma unroll
            for (int i = 0; i < 4; i++) {
                int idx = tid + i * 256;
                int r = idx >> 3, c = idx & 7;
                pa[i] = *(const float4*)(A + (size_t)(m0 + r) * K + (kb + 1) * 32 + c * 4);
            }
            #pragma unroll
            for (int i = 0; i < 2; i++) {
                int idx = tid + i * 256;
                int k = idx & 31, c = idx >> 5;
                pw[i] = *(const float4*)(W + (size_t)((kb + 1) * 32 + k) * N + n0 + c * 4);
            }
        }

        const uint32_t ab = sb + cur * 16384;
        const uint32_t bb = sb + 32768 + cur * 8192;
        #pragma unroll
        for (int kt = 0; kt < 4; kt++) {
            uint32_t af[2][4], bf[2][4];
            #pragma unroll
            for (int mt = 0; mt < 2; mt++) {
                int mr = wm * 32 + mt * 16 + (lane & 7) + ((lane >> 3) & 1) * 8;
                ldsm4(af[mt], ab + mr * 128 + SWZ(mr, kt * 32 + (lane >> 4) * 16));
            }
            #pragma unroll
            for (int p = 0; p < 2; p++) {
                int nr = wn * 32 + p * 16 + (lane & 7) + (lane >> 4) * 8;
                ldsm4(bf[p], bb + nr * 128 + SWZ(nr, kt * 32 + ((lane >> 3) & 1) * 16));
            }
            #pragma unroll
            for (int mt = 0; mt < 2; mt++)
                #pragma unroll
                for (int p = 0; p < 2; p++) {
                    mma8(acc[mt][2 * p],     af[mt], bf[p][0], bf[p][1]);
                    mma8(acc[mt][2 * p + 1], af[mt], bf[p][2], bf[p][3]);
                }
        }

        if (kb + 1 < nkb) {
            char* ad = smg + (cur ^ 1) * 16384;
            char* bd = smg + 32768 + (cur ^ 1) * 8192;
            #pragma unroll
            for (int i = 0; i < 4; i++) {
                int idx = tid + i * 256;
                int r = idx >> 3, c = idx & 7;
                float4 v = pa[i];
                v.x = tf32r(v.x); v.y = tf32r(v.y); v.z = tf32r(v.z); v.w = tf32r(v.w);
                *(float4*)(ad + r * 128 + SWZ(r, c * 16)) = v;
            }
            #pragma unroll
            for (int i = 0; i < 2; i++) {
                int idx = tid + i * 256;
                int k = idx & 31, c = idx >> 5;
                float vv[4] = { tf32r(pw[i].x), tf32r(pw[i].y), tf32r(pw[i].z), tf32r(pw[i].w) };
                #pragma unroll
                for (int j = 0; j < 4; j++) {
                    int n = c * 4 + j;
                    *(float*)(bd + n * 128 + SWZ(n, k * 4)) = vv[j];
                }
            }
        }
        __syncthreads();
    }

    // epilogue
    #pragma unroll
    for (int nt = 0; nt < 4; nt++) {
        int col = n0 + wn * 32 + nt * 8 + 2 * t;
        float2 bv = *(const float2*)(bias + col);
        #pragma unroll
        for (int mt = 0; mt < 2; mt++) {
            int row = m0 + wm * 32 + mt * 16 + g;
            float o0 = acc[mt][nt][0] + bv.x, o1 = acc[mt][nt][1] + bv.y;
            float o2 = acc[mt][nt][2] + bv.x, o3 = acc[mt][nt][3] + bv.y;
            if (MODE == 0) {
                *(float2*)(C + (size_t)row * N + col) =
                    make_float2(tf32r(o0 * oscale), tf32r(o1 * oscale));
                *(float2*)(C + (size_t)(row + 8) * N + col) =
                    make_float2(tf32r(o2 * oscale), tf32r(o3 * oscale));
            } else if (MODE == 1) {
                C[(size_t)col * M + row]           = tf32r(o0 * oscale);
                C[(size_t)(col + 1) * M + row]     = tf32r(o1 * oscale);
                C[(size_t)col * M + row + 8]       = tf32r(o2 * oscale);
                C[(size_t)(col + 1) * M + row + 8] = tf32r(o3 * oscale);
            } else {
                *(float2*)(C + (size_t)row * N + col) = make_float2(o0, o1);
                *(float2*)(C + (size_t)(row + 8) * N + col) = make_float2(o2, o3);
            }
        }
    }
}

// ============================================================================
// Flash attention: ldmatrix fragments + cp.async double-buffered K/V.
// CTA = 128 q-rows x (head, batch); 8 warps; warp owns 16 q-rows.
// Smem: Q 128x32 (16KB) | K 2x 64x32 (16KB) | Vt 2x 32x64 (16KB) = 48KB.
// ============================================================================
__global__ __launch_bounds__(256, 2) void attn_tc(
    const float* __restrict__ gq, const float* __restrict__ gk,
    const float* __restrict__ gvt, const float* __restrict__ mask,
    float* __restrict__ gctx)
{
    __shared__ char sma[49152];
    const uint32_t QB = smem_u32(sma);

    const int tid = threadIdx.x;
    const int w = tid >> 5, lane = tid & 31;
    const int g = lane >> 2, t = lane & 3;
    const int h = blockIdx.x, qt = blockIdx.y, b = blockIdx.z;

    const float* qsrc  = gq + ((size_t)(b * SEQ + qt * 128)) * KDIM + h * HDIM;
    const float* ksrc  = gk + ((size_t)(b * SEQ)) * KDIM + h * HDIM;
    const float* vtsrc = gvt + (size_t)(h * HDIM) * MTOT + b * SEQ;

    // prologue: Q + K0 + V0 via cp.async
    #pragma unroll
    for (int i = 0; i < 4; i++) {
        int idx = tid + i * 256;
        int r = idx >> 3, c = idx & 7;
        CP16(QB + r * 128 + SWZ(r, c * 16), qsrc + (size_t)r * KDIM + c * 4);
    }
    #pragma unroll
    for (int i = 0; i < 2; i++) {
        int idx = tid + i * 256;
        int r = idx >> 3, c = idx & 7;
        CP16(QB + 16384 + r * 128 + SWZ(r, c * 16), ksrc + (size_t)r * KDIM + c * 4);
    }
    #pragma unroll
    for (int i = 0; i < 2; i++) {
        int idx = tid + i * 256;
        int r = idx >> 4, c = idx & 15;
        CP16(QB + 32768 + r * 256 + SWZ(r, c * 16), vtsrc + (size_t)r * MTOT + c * 4);
    }
    CPCOMMIT(); CPWAIT0();
    __syncthreads();

    // Q fragments (held for whole kernel)
    uint32_t qf[4][4];
    #pragma unroll
    for (int kt = 0; kt < 4; kt++) {
        int mr = w * 16 + (lane & 7) + ((lane >> 3) & 1) * 8;
        ldsm4(qf[kt], QB + mr * 128 + SWZ(mr, kt * 32 + (lane >> 4) * 16));
    }

    const float* mr0 = mask + (size_t)b * SEQ * SEQ
                     + (size_t)(qt * 128 + w * 16 + g) * SEQ + 2 * t;
    const float* mr1 = mr0 + (size_t)8 * SEQ;

    float ctx[4][4];
    #pragma unroll
    for (int i = 0; i < 4; i++)
        #pragma unroll
        for (int j = 0; j < 4; j++) ctx[i][j] = 0.f;
    float lg = 0.f, lh = 0.f;

    const int srcA = (lane & ~3) | (t >> 1);
    const int srcB = srcA + 2;

    for (int kt0 = 0; kt0 < 32; kt0++) {
        const int cur = kt0 & 1;

        if (kt0 < 31) {
            const uint32_t kd = QB + 16384 + (cur ^ 1) * 8192;
            const uint32_t vd = QB + 32768 + (cur ^ 1) * 8192;
            #pragma unroll
            for (int i = 0; i < 2; i++) {
                int idx = tid + i * 256;
                int r = idx >> 3, c = idx & 7;
                CP16(kd + r * 128 + SWZ(r, c * 16),
                     ksrc + (size_t)((kt0 + 1) * 64 + r) * KDIM + c * 4);
            }
            #pragma unroll
            for (int i = 0; i < 2; i++) {
                int idx = tid + i * 256;
                int r = idx >> 4, c = idx & 15;
                CP16(vd + r * 256 + SWZ(r, c * 16),
                     vtsrc + (size_t)r * MTOT + (kt0 + 1) * 64 + c * 4);
            }
            CPCOMMIT();
        }

        // mask prefetch
        float2 m0v[8], m1v[8];
        #pragma unroll
        for (int nt = 0; nt < 8; nt++) {
            m0v[nt] = *(const float2*)(mr0 + kt0 * 64 + nt * 8);
            m1v[nt] = *(const float2*)(mr1 + kt0 * 64 + nt * 8);
        }

        // S = Q @ K^T
        float sc[8][4];
        #pragma unroll
        for (int nt = 0; nt < 8; nt++)
            #pragma unroll
            for (int i = 0; i < 4; i++) sc[nt][i] = 0.f;
        const uint32_t kbse = QB + 16384 + cur * 8192;
        #pragma unroll
        for (int kt = 0; kt < 4; kt++) {
            #pragma unroll
            for (int p = 0; p < 4; p++) {
                int kr = p * 16 + (lane & 7) + (lane >> 4) * 8;
                uint32_t bf[4];
                ldsm4(bf, kbse + kr * 128 + SWZ(kr, kt * 32 + ((lane >> 3) & 1) * 16));
                mma8(sc[2 * p],     qf[kt], bf[0], bf[1]);
                mma8(sc[2 * p + 1], qf[kt], bf[2], bf[3]);
            }
        }

        // p = exp2(s + mask*log2e)  (s pre-scaled via Q projection)
        #pragma unroll
        for (int nt = 0; nt < 8; nt++) {
            float p0 = ex2f(__fmaf_rn(m0v[nt].x, LOG2E, sc[nt][0]));
            float p1 = ex2f(__fmaf_rn(m0v[nt].y, LOG2E, sc[nt][1]));
            float p2 = ex2f(__fmaf_rn(m1v[nt].x, LOG2E, sc[nt][2]));
            float p3 = ex2f(__fmaf_rn(m1v[nt].y, LOG2E, sc[nt][3]));
            lg += p0 + p1;
            lh += p2 + p3;
            sc[nt][0] = tf32r(p0); sc[nt][1] = tf32r(p1);
            sc[nt][2] = tf32r(p2); sc[nt][3] = tf32r(p3);
        }

        // ctx += P @ V
        const uint32_t vbse = QB + 32768 + cur * 8192;
        #pragma unroll
        for (int kc = 0; kc < 8; kc++) {
            uint32_t a[4];
            float x0, x1;
            x0 = __shfl_sync(0xFFFFFFFFu, sc[kc][0], srcA);
            x1 = __shfl_sync(0xFFFFFFFFu, sc[kc][1], srcA);
            a[0] = __float_as_uint((t & 1) ? x1 : x0);
            x0 = __shfl_sync(0xFFFFFFFFu, sc[kc][2], srcA);
            x1 = __shfl_sync(0xFFFFFFFFu, sc[kc][3], srcA);
            a[1] = __float_as_uint((t & 1) ? x1 : x0);
            x0 = __shfl_sync(0xFFFFFFFFu, sc[kc][0], srcB);
            x1 = __shfl_sync(0xFFFFFFFFu, sc[kc][1], srcB);
            a[2] = __float_as_uint((t & 1) ? x1 : x0);
            x0 = __shfl_sync(0xFFFFFFFFu, sc[kc][2], srcB);
            x1 = __shfl_sync(0xFFFFFFFFu, sc[kc][3], srcB);
            a[3] = __float_as_uint((t & 1) ? x1 : x0);
            #pragma unroll
            for (int p = 0; p < 2; p++) {
                int dr = p * 16 + (lane & 7) + (lane >> 4) * 8;
                uint32_t bf[4];
                ldsm4(bf, vbse + dr * 256 + SWZ(dr, kc * 32 + ((lane >> 3) & 1) * 16));
                mma8(ctx[2 * p],     a, bf[0], bf[1]);
                mma8(ctx[2 * p + 1], a, bf[2], bf[3]);
            }
        }

        if (kt0 < 31) CPWAIT0();
        __syncthreads();
    }

    lg += __shfl_xor_sync(0xFFFFFFFFu, lg, 1);
    lg += __shfl_xor_sync(0xFFFFFFFFu, lg, 2);
    lh += __shfl_xor_sync(0xFFFFFFFFu, lh, 1);
    lh += __shfl_xor_sync(0xFFFFFFFFu, lh, 2);
    float ig = 1.0f / lg, ih = 1.0f / lh;

    size_t rbase = ((size_t)(b * SEQ + qt * 128 + w * 16 + g)) * VDIM + h * HDIM;
    #pragma unroll
    for (int nt = 0; nt < 4; nt++) {
        int col = nt * 8 + 2 * t;
        *(float2*)(gctx + rbase + col) =
            make_float2(ctx[nt][0] * ig, ctx[nt][1] * ig);
        *(float2*)(gctx + rbase + (size_t)8 * VDIM + col) =
            make_float2(ctx[nt][2] * ih, ctx[nt][3] * ih);
    }
}

// ---------------- launch ----------------
extern "C" void kernel_launch(void* const* d_in, const int* in_sizes, int n_in,
                              void* d_out, int out_size)
{
    const float* V    = (const float*)d_in[0];
    const float* Q    = (const float*)d_in[1];
    const float* K    = (const float*)d_in[2];
    const float* mask = (const float*)d_in[3];
    const float* Wq   = (const float*)d_in[4];
    const float* bq   = (const float*)d_in[5];
    const float* Wk   = (const float*)d_in[6];
    const float* bk   = (const float*)d_in[7];
    const float* Wv   = (const float*)d_in[8];
    const float* bv   = (const float*)d_in[9];
    const float* Wo   = (const float*)d_in[10];
    const float* bo   = (const float*)d_in[11];
    float* out = (float*)d_out;

    float *dq, *dk, *dvt, *dctx;
    cudaGetSymbolAddress((void**)&dq,   g_q);
    cudaGetSymbolAddress((void**)&dk,   g_k);
    cudaGetSymbolAddress((void**)&dvt,  g_vt);
    cudaGetSymbolAddress((void**)&dctx, g_ctx);

    // projections: M=4096, N=256, K=512
    dim3 gridP(KDIM / 64, MTOT / 128);
    gemm_tc<0><<<gridP, 256>>>(Q, Wq, bq, dq,  MTOT, KDIM, DMODEL, LOG2E / 16.0f);
    gemm_tc<0><<<gridP, 256>>>(K, Wk, bk, dk,  MTOT, KDIM, DMODEL, 1.0f);
    gemm_tc<1><<<gridP, 256>>>(V, Wv, bv, dvt, MTOT, VDIM, DMODEL, 1.0f);

    // attention
    dim3 gridA(NHEADS, SEQ / 128, BATCH);
    attn_tc<<<gridA, 256>>>(dq, dk, dvt, mask, dctx);

    // output projection: M=4096, N=512, K=256
    dim3 gridO(ODIM / 64, MTOT / 128);
    gemm_tc<2><<<gridO, 256>>>(dctx, Wo, bo, out, MTOT, ODIM, VDIM, 1.0f);
}

// round 8
// speedup vs baseline: 3.0923x; 1.0125x over previous
#include <cuda_runtime.h>
#include <cstdint>

// ---------------- problem constants ----------------
#define BATCH 2
#define SEQ 2048
#define DMODEL 512
#define KDIM 256
#define VDIM 256
#define ODIM 512
#define NHEADS 8
#define HDIM 32
#define LOG2E 1.4426950408889634f
#define MTOT (BATCH * SEQ)          // 4096

// scratch
__device__ float g_q[MTOT * KDIM];
__device__ float g_k[MTOT * KDIM];
__device__ float g_vt[KDIM * MTOT];    // V projection, transposed: [n=256][m=4096]
__device__ float g_ctx[MTOT * VDIM];   // tf32-rounded context
__device__ float g_wqt[KDIM * DMODEL]; // Wq^T [256][512], tf32-rounded
__device__ float g_wkt[KDIM * DMODEL];
__device__ float g_wvt[VDIM * DMODEL];
__device__ float g_wot[ODIM * VDIM];   // Wo^T [512][256]

// ---------------- helpers ----------------
__device__ __forceinline__ uint32_t smem_u32(const void* p) {
    uint32_t a;
    asm("{ .reg .u64 t; cvta.to.shared.u64 t, %1; cvt.u32.u64 %0, t; }" : "=r"(a) : "l"(p));
    return a;
}
__device__ __forceinline__ float tf32r(float x) {
    float y; asm("cvt.rna.tf32.f32 %0, %1;" : "=f"(y) : "f"(x)); return y;
}
__device__ __forceinline__ float ex2f(float x) {
    float y; asm("ex2.approx.ftz.f32 %0, %1;" : "=f"(y) : "f"(x)); return y;
}
__device__ __forceinline__ void mma8(float* c, const uint32_t* a, uint32_t b0, uint32_t b1) {
    asm volatile(
        "mma.sync.aligned.m16n8k8.row.col.f32.tf32.tf32.f32 "
        "{%0,%1,%2,%3}, {%4,%5,%6,%7}, {%8,%9}, {%0,%1,%2,%3};"
        : "+f"(c[0]), "+f"(c[1]), "+f"(c[2]), "+f"(c[3])
        : "r"(a[0]), "r"(a[1]), "r"(a[2]), "r"(a[3]), "r"(b0), "r"(b1));
}
__device__ __forceinline__ void ldsm4(uint32_t* r, uint32_t a) {
    asm volatile("ldmatrix.sync.aligned.m8n8.x4.shared.b16 {%0,%1,%2,%3}, [%4];"
        : "=r"(r[0]), "=r"(r[1]), "=r"(r[2]), "=r"(r[3]) : "r"(a));
}
#define CP16(dst, src) \
    asm volatile("cp.async.ca.shared.global [%0], [%1], 16;" :: "r"(dst), "l"(src))
#define CPCOMMIT() asm volatile("cp.async.commit_group;" ::: "memory")
#define CPWAIT0()  asm volatile("cp.async.wait_group 0;" ::: "memory")
#define STS64(addr, v0, v1) \
    asm volatile("st.shared.v2.f32 [%0], {%1, %2};" :: "r"(addr), "f"(v0), "f"(v1))

#define SWZ(row, col) ((uint32_t)(col) ^ ((uint32_t)((row) & 7) << 4))

// ============================================================================
// Weight transpose + tf32 round: WT[n][k] = tf32r(W[k][n])
// ============================================================================
__global__ void wprep(const float* __restrict__ W, float* __restrict__ WT, int K, int N) {
    __shared__ float ts[32][33];
    const int n0 = blockIdx.x * 32, k0 = blockIdx.y * 32;
    const int tx = threadIdx.x, ty = threadIdx.y;   // 32 x 8
    #pragma unroll
    for (int i = 0; i < 4; i++)
        ts[ty + i * 8][tx] = W[(size_t)(k0 + ty + i * 8) * N + n0 + tx];
    __syncthreads();
    #pragma unroll
    for (int i = 0; i < 4; i++)
        WT[(size_t)(n0 + ty + i * 8) * K + k0 + tx] = tf32r(ts[tx][ty + i * 8]);
}

// ============================================================================
// tf32 GEMM + bias. A[M,K] @ WT[N,K]^T + bias.
// BM=128, BN=64, BK=32; 8 warps 4(m)x2(n); warp tile 32x32.
// B staged via cp.async (WT pre-rounded). A: PRE_A ? cp.async : register+round.
// MODE 0: C[m][n]=tf32r((acc+b)*s)  MODE 1: Ct[n][M]=tf32r((acc+b)*s)  MODE 2: C=acc+b
// ============================================================================
template<int MODE, bool PRE_A>
__global__ __launch_bounds__(256) void gemm_tc(
    const float* __restrict__ A, const float* __restrict__ WT,
    const float* __restrict__ bias, float* __restrict__ C,
    int M, int N, int K, float oscale)
{
    __shared__ char smg[49152];   // A 2x16KB @0, B 2x8KB @32768
    const uint32_t sb = smem_u32(smg);

    const int tid = threadIdx.x;
    const int w = tid >> 5, lane = tid & 31;
    const int g = lane >> 2, t = lane & 3;
    const int wm = w >> 1, wn = w & 1;
    const int m0 = blockIdx.y * 128, n0 = blockIdx.x * 64;

    float acc[2][4][4];
    #pragma unroll
    for (int i = 0; i < 2; i++)
        #pragma unroll
        for (int j = 0; j < 4; j++)
            #pragma unroll
            for (int q = 0; q < 4; q++) acc[i][j][q] = 0.f;

    const int nkb = K >> 5;

    // prologue: stage block 0
    #pragma unroll
    for (int i = 0; i < 2; i++) {
        int idx = tid + i * 256;
        int n = idx >> 3, c = idx & 7;
        CP16(sb + 32768 + n * 128 + SWZ(n, c * 16), WT + (size_t)(n0 + n) * K + c * 4);
    }
    if (PRE_A) {
        #pragma unroll
        for (int i = 0; i < 4; i++) {
            int idx = tid + i * 256;
            int r = idx >> 3, c = idx & 7;
            CP16(sb + r * 128 + SWZ(r, c * 16), A + (size_t)(m0 + r) * K + c * 4);
        }
    } else {
        #pragma unroll
        for (int i = 0; i < 4; i++) {
            int idx = tid + i * 256;
            int r = idx >> 3, c = idx & 7;
            float4 v = *(const float4*)(A + (size_t)(m0 + r) * K + c * 4);
            v.x = tf32r(v.x); v.y = tf32r(v.y); v.z = tf32r(v.z); v.w = tf32r(v.w);
            *(float4*)(smg + r * 128 + SWZ(r, c * 16)) = v;
        }
    }
    CPCOMMIT(); CPWAIT0();
    __syncthreads();

    for (int kb = 0; kb < nkb; kb++) {
        const int cur = kb & 1;

        float4 pa[4];
        if (kb + 1 < nkb) {
            // prefetch next B (and A if pre-rounded) via cp.async
            const uint32_t bd = sb + 32768 + (cur ^ 1) * 8192;
            #pragma unroll
            for (int i = 0; i < 2; i++) {
                int idx = tid + i * 256;
                int n = idx >> 3, c = idx & 7;
                CP16(bd + n * 128 + SWZ(n, c * 16),
                     WT + (size_t)(n0 + n) * K + (kb + 1) * 32 + c * 4);
            }
            if (PRE_A) {
                const uint32_t ad = sb + (cur ^ 1) * 16384;
                #pragma unroll
                for (int i = 0; i < 4; i++) {
                    int idx = tid + i * 256;
                    int r = idx >> 3, c = idx & 7;
                    CP16(ad + r * 128 + SWZ(r, c * 16),
                         A + (size_t)(m0 + r) * K + (kb + 1) * 32 + c * 4);
                }
            } else {
                #pragma unroll
                for (int i = 0; i < 4; i++) {
                    int idx = tid + i * 256;
                    int r = idx >> 3, c = idx & 7;
                    pa[i] = *(const float4*)(A + (size_t)(m0 + r) * K + (kb + 1) * 32 + c * 4);
                }
            }
            CPCOMMIT();
        }

        const uint32_t ab = sb + cur * 16384;
        const uint32_t bb = sb + 32768 + cur * 8192;
        #pragma unroll
        for (int kt = 0; kt < 4; kt++) {
            uint32_t af[2][4], bf[2][4];
            #pragma unroll
            for (int mt = 0; mt < 2; mt++) {
                int mr = wm * 32 + mt * 16 + (lane & 7) + ((lane >> 3) & 1) * 8;
                ldsm4(af[mt], ab + mr * 128 + SWZ(mr, kt * 32 + (lane >> 4) * 16));
            }
            #pragma unroll
            for (int p = 0; p < 2; p++) {
                int nr = wn * 32 + p * 16 + (lane & 7) + (lane >> 4) * 8;
                ldsm4(bf[p], bb + nr * 128 + SWZ(nr, kt * 32 + ((lane >> 3) & 1) * 16));
            }
            #pragma unroll
            for (int mt = 0; mt < 2; mt++)
                #pragma unroll
                for (int p = 0; p < 2; p++) {
                    mma8(acc[mt][2 * p],     af[mt], bf[p][0], bf[p][1]);
                    mma8(acc[mt][2 * p + 1], af[mt], bf[p][2], bf[p][3]);
                }
        }

        if (!PRE_A && kb + 1 < nkb) {
            char* ad = smg + (cur ^ 1) * 16384;
            #pragma unroll
            for (int i = 0; i < 4; i++) {
                int idx = tid + i * 256;
                int r = idx >> 3, c = idx & 7;
                float4 v = pa[i];
                v.x = tf32r(v.x); v.y = tf32r(v.y); v.z = tf32r(v.z); v.w = tf32r(v.w);
                *(float4*)(ad + r * 128 + SWZ(r, c * 16)) = v;
            }
        }
        CPWAIT0();
        __syncthreads();
    }

    // epilogue
    #pragma unroll
    for (int nt = 0; nt < 4; nt++) {
        int col = n0 + wn * 32 + nt * 8 + 2 * t;
        float2 bv = *(const float2*)(bias + col);
        #pragma unroll
        for (int mt = 0; mt < 2; mt++) {
            int row = m0 + wm * 32 + mt * 16 + g;
            float o0 = acc[mt][nt][0] + bv.x, o1 = acc[mt][nt][1] + bv.y;
            float o2 = acc[mt][nt][2] + bv.x, o3 = acc[mt][nt][3] + bv.y;
            if (MODE == 0) {
                *(float2*)(C + (size_t)row * N + col) =
                    make_float2(tf32r(o0 * oscale), tf32r(o1 * oscale));
                *(float2*)(C + (size_t)(row + 8) * N + col) =
                    make_float2(tf32r(o2 * oscale), tf32r(o3 * oscale));
            } else if (MODE == 1) {
                C[(size_t)col * M + row]           = tf32r(o0 * oscale);
                C[(size_t)(col + 1) * M + row]     = tf32r(o1 * oscale);
                C[(size_t)col * M + row + 8]       = tf32r(o2 * oscale);
                C[(size_t)(col + 1) * M + row + 8] = tf32r(o3 * oscale);
            } else {
                *(float2*)(C + (size_t)row * N + col) = make_float2(o0, o1);
                *(float2*)(C + (size_t)(row + 8) * N + col) = make_float2(o2, o3);
            }
        }
    }
}

// ============================================================================
// Flash attention. P repack via per-warp smem staging (STS.64 + ldmatrix),
// cp.async double-buffered K/V.
// Smem: Q 16KB @0 | K 2x8KB @16384 | Vt 2x8KB @32768 | P 8x4KB @49152 = 80KB.
// ============================================================================
#define ATTN_SMEM 81920

__global__ __launch_bounds__(256, 2) void attn_tc(
    const float* __restrict__ gq, const float* __restrict__ gk,
    const float* __restrict__ gvt, const float* __restrict__ mask,
    float* __restrict__ gctx)
{
    extern __shared__ char sma[];
    const uint32_t QB = smem_u32(sma);

    const int tid = threadIdx.x;
    const int w = tid >> 5, lane = tid & 31;
    const int g = lane >> 2, t = lane & 3;
    const int h = blockIdx.x, qt = blockIdx.y, b = blockIdx.z;

    const float* qsrc  = gq + ((size_t)(b * SEQ + qt * 128)) * KDIM + h * HDIM;
    const float* ksrc  = gk + ((size_t)(b * SEQ)) * KDIM + h * HDIM;
    const float* vtsrc = gvt + (size_t)(h * HDIM) * MTOT + b * SEQ;

    // prologue: Q + K0 + V0 via cp.async
    #pragma unroll
    for (int i = 0; i < 4; i++) {
        int idx = tid + i * 256;
        int r = idx >> 3, c = idx & 7;
        CP16(QB + r * 128 + SWZ(r, c * 16), qsrc + (size_t)r * KDIM + c * 4);
    }
    #pragma unroll
    for (int i = 0; i < 2; i++) {
        int idx = tid + i * 256;
        int r = idx >> 3, c = idx & 7;
        CP16(QB + 16384 + r * 128 + SWZ(r, c * 16), ksrc + (size_t)r * KDIM + c * 4);
    }
    #pragma unroll
    for (int i = 0; i < 2; i++) {
        int idx = tid + i * 256;
        int r = idx >> 4, c = idx & 15;
        CP16(QB + 32768 + r * 256 + SWZ(r, c * 16), vtsrc + (size_t)r * MTOT + c * 4);
    }
    CPCOMMIT(); CPWAIT0();
    __syncthreads();

    // Q fragments (held for whole kernel)
    uint32_t qf[4][4];
    #pragma unroll
    for (int kt = 0; kt < 4; kt++) {
        int mr = w * 16 + (lane & 7) + ((lane >> 3) & 1) * 8;
        ldsm4(qf[kt], QB + mr * 128 + SWZ(mr, kt * 32 + (lane >> 4) * 16));
    }

    const float* mr0 = mask + (size_t)b * SEQ * SEQ
                     + (size_t)(qt * 128 + w * 16 + g) * SEQ + 2 * t;
    const float* mr1 = mr0 + (size_t)8 * SEQ;

    float ctx[4][4];
    #pragma unroll
    for (int i = 0; i < 4; i++)
        #pragma unroll
        for (int j = 0; j < 4; j++) ctx[i][j] = 0.f;
    float lg = 0.f, lh = 0.f;

    const uint32_t PB = QB + 49152 + w * 4096;   // per-warp P tile: 16 rows x 256B
    const uint32_t ps0 = PB + g * 256;           // row g
    const uint32_t ps1 = PB + (g + 8) * 256;     // row g+8
    const uint32_t pr = (lane & 7) + ((lane >> 3) & 1) * 8;
    const uint32_t prow = PB + pr * 256;         // ldmatrix row base
    const uint32_t pcol0 = (lane >> 4) * 16;     // 16B-half select
    const uint32_t pswz = (pr & 7) << 4;         // row swizzle

    for (int kt0 = 0; kt0 < 32; kt0++) {
        const int cur = kt0 & 1;

        if (kt0 < 31) {
            const uint32_t kd = QB + 16384 + (cur ^ 1) * 8192;
            const uint32_t vd = QB + 32768 + (cur ^ 1) * 8192;
            #pragma unroll
            for (int i = 0; i < 2; i++) {
                int idx = tid + i * 256;
                int r = idx >> 3, c = idx & 7;
                CP16(kd + r * 128 + SWZ(r, c * 16),
                     ksrc + (size_t)((kt0 + 1) * 64 + r) * KDIM + c * 4);
            }
            #pragma unroll
            for (int i = 0; i < 2; i++) {
                int idx = tid + i * 256;
                int r = idx >> 4, c = idx & 15;
                CP16(vd + r * 256 + SWZ(r, c * 16),
                     vtsrc + (size_t)r * MTOT + (kt0 + 1) * 64 + c * 4);
            }
            CPCOMMIT();
        }

        // mask prefetch
        float2 m0v[8], m1v[8];
        #pragma unroll
        for (int nt = 0; nt < 8; nt++) {
            m0v[nt] = *(const float2*)(mr0 + kt0 * 64 + nt * 8);
            m1v[nt] = *(const float2*)(mr1 + kt0 * 64 + nt * 8);
        }

        // S = Q @ K^T
        float sc[8][4];
        #pragma unroll
        for (int nt = 0; nt < 8; nt++)
            #pragma unroll
            for (int i = 0; i < 4; i++) sc[nt][i] = 0.f;
        const uint32_t kbse = QB + 16384 + cur * 8192;
        #pragma unroll
        for (int kt = 0; kt < 4; kt++) {
            #pragma unroll
            for (int p = 0; p < 4; p++) {
                int kr = p * 16 + (lane & 7) + (lane >> 4) * 8;
                uint32_t bf[4];
                ldsm4(bf, kbse + kr * 128 + SWZ(kr, kt * 32 + ((lane >> 3) & 1) * 16));
                mma8(sc[2 * p],     qf[kt], bf[0], bf[1]);
                mma8(sc[2 * p + 1], qf[kt], bf[2], bf[3]);
            }
        }

        // p = exp2(s + mask*log2e); store P tile to per-warp smem
        #pragma unroll
        for (int nt = 0; nt < 8; nt++) {
            float p0 = ex2f(__fmaf_rn(m0v[nt].x, LOG2E, sc[nt][0]));
            float p1 = ex2f(__fmaf_rn(m0v[nt].y, LOG2E, sc[nt][1]));
            float p2 = ex2f(__fmaf_rn(m1v[nt].x, LOG2E, sc[nt][2]));
            float p3 = ex2f(__fmaf_rn(m1v[nt].y, LOG2E, sc[nt][3]));
            lg += p0 + p1;
            lh += p2 + p3;
            uint32_t cb = (uint32_t)(nt * 32 + t * 8);
            STS64(ps0 + (cb ^ ((g & 7) << 4)),       tf32r(p0), tf32r(p1));
            STS64(ps1 + (cb ^ (((g + 8) & 7) << 4)), tf32r(p2), tf32r(p3));
        }
        __syncwarp();

        // ctx += P @ V   (swizzle applied to FULL column offset, inside the loop)
        const uint32_t vbse = QB + 32768 + cur * 8192;
        #pragma unroll
        for (int kc = 0; kc < 8; kc++) {
            uint32_t a[4];
            ldsm4(a, prow + (((uint32_t)(kc * 32) + pcol0) ^ pswz));
            #pragma unroll
            for (int p = 0; p < 2; p++) {
                int dr = p * 16 + (lane & 7) + (lane >> 4) * 8;
                uint32_t bf[4];
                ldsm4(bf, vbse + dr * 256 + SWZ(dr, kc * 32 + ((lane >> 3) & 1) * 16));
                mma8(ctx[2 * p],     a, bf[0], bf[1]);
                mma8(ctx[2 * p + 1], a, bf[2], bf[3]);
            }
        }

        if (kt0 < 31) CPWAIT0();
        __syncthreads();
    }

    lg += __shfl_xor_sync(0xFFFFFFFFu, lg, 1);
    lg += __shfl_xor_sync(0xFFFFFFFFu, lg, 2);
    lh += __shfl_xor_sync(0xFFFFFFFFu, lh, 1);
    lh += __shfl_xor_sync(0xFFFFFFFFu, lh, 2);
    float ig = 1.0f / lg, ih = 1.0f / lh;

    // write tf32-rounded ctx (feeds cp.async-staged output GEMM)
    size_t rbase = ((size_t)(b * SEQ + qt * 128 + w * 16 + g)) * VDIM + h * HDIM;
    #pragma unroll
    for (int nt = 0; nt < 4; nt++) {
        int col = nt * 8 + 2 * t;
        *(float2*)(gctx + rbase + col) =
            make_float2(tf32r(ctx[nt][0] * ig), tf32r(ctx[nt][1] * ig));
        *(float2*)(gctx + rbase + (size_t)8 * VDIM + col) =
            make_float2(tf32r(ctx[nt][2] * ih), tf32r(ctx[nt][3] * ih));
    }
}

// ---------------- launch ----------------
extern "C" void kernel_launch(void* const* d_in, const int* in_sizes, int n_in,
                              void* d_out, int out_size)
{
    const float* V    = (const float*)d_in[0];
    const float* Q    = (const float*)d_in[1];
    const float* K    = (const float*)d_in[2];
    const float* mask = (const float*)d_in[3];
    const float* Wq   = (const float*)d_in[4];
    const float* bq   = (const float*)d_in[5];
    const float* Wk   = (const float*)d_in[6];
    const float* bk   = (const float*)d_in[7];
    const float* Wv   = (const float*)d_in[8];
    const float* bv   = (const float*)d_in[9];
    const float* Wo   = (const float*)d_in[10];
    const float* bo   = (const float*)d_in[11];
    float* out = (float*)d_out;

    float *dq, *dk, *dvt, *dctx, *dwqt, *dwkt, *dwvt, *dwot;
    cudaGetSymbolAddress((void**)&dq,   g_q);
    cudaGetSymbolAddress((void**)&dk,   g_k);
    cudaGetSymbolAddress((void**)&dvt,  g_vt);
    cudaGetSymbolAddress((void**)&dctx, g_ctx);
    cudaGetSymbolAddress((void**)&dwqt, g_wqt);
    cudaGetSymbolAddress((void**)&dwkt, g_wkt);
    cudaGetSymbolAddress((void**)&dwvt, g_wvt);
    cudaGetSymbolAddress((void**)&dwot, g_wot);

    // weight transpose + round (tiny)
    dim3 tb(32, 8);
    wprep<<<dim3(KDIM / 32, DMODEL / 32), tb>>>(Wq, dwqt, DMODEL, KDIM);
    wprep<<<dim3(KDIM / 32, DMODEL / 32), tb>>>(Wk, dwkt, DMODEL, KDIM);
    wprep<<<dim3(VDIM / 32, DMODEL / 32), tb>>>(Wv, dwvt, DMODEL, VDIM);
    wprep<<<dim3(ODIM / 32, VDIM / 32),   tb>>>(Wo, dwot, VDIM, ODIM);

    // projections: M=4096, N=256, K=512
    dim3 gridP(KDIM / 64, MTOT / 128);
    gemm_tc<0, false><<<gridP, 256>>>(Q, dwqt, bq, dq,  MTOT, KDIM, DMODEL, LOG2E / 16.0f);
    gemm_tc<0, false><<<gridP, 256>>>(K, dwkt, bk, dk,  MTOT, KDIM, DMODEL, 1.0f);
    gemm_tc<1, false><<<gridP, 256>>>(V, dwvt, bv, dvt, MTOT, VDIM, DMODEL, 1.0f);

    // attention
    cudaFuncSetAttribute(attn_tc, cudaFuncAttributeMaxDynamicSharedMemorySize, ATTN_SMEM);
    dim3 gridA(NHEADS, SEQ / 128, BATCH);
    attn_tc<<<gridA, 256, ATTN_SMEM>>>(dq, dk, dvt, mask, dctx);

    // output projection: M=4096, N=512, K=256 (both operands pre-rounded)
    dim3 gridO(ODIM / 64, MTOT / 128);
    gemm_tc<2, true><<<gridO, 256>>>(dctx, dwot, bo, out, MTOT, ODIM, VDIM, 1.0f);
}

// round 9
// speedup vs baseline: 3.5535x; 1.1492x over previous
#include <cuda_runtime.h>
#include <cstdint>

// ---------------- problem constants ----------------
#define BATCH 2
#define SEQ 2048
#define DMODEL 512
#define KDIM 256
#define VDIM 256
#define ODIM 512
#define NHEADS 8
#define HDIM 32
#define LOG2E 1.4426950408889634f
#define MTOT (BATCH * SEQ)          // 4096

// scratch
__device__ float g_q[MTOT * KDIM];
__device__ float g_k[MTOT * KDIM];
__device__ float g_vt[KDIM * MTOT];    // V projection, transposed: [n=256][m=4096]
__device__ float g_ctx[MTOT * VDIM];   // tf32-rounded context
__device__ float g_wqt[KDIM * DMODEL]; // Wq^T [256][512], tf32-rounded
__device__ float g_wkt[KDIM * DMODEL];
__device__ float g_wvt[VDIM * DMODEL];
__device__ float g_wot[ODIM * VDIM];   // Wo^T [512][256]

// ---------------- helpers ----------------
__device__ __forceinline__ uint32_t smem_u32(const void* p) {
    uint32_t a;
    asm("{ .reg .u64 t; cvta.to.shared.u64 t, %1; cvt.u32.u64 %0, t; }" : "=r"(a) : "l"(p));
    return a;
}
__device__ __forceinline__ float tf32r(float x) {
    float y; asm("cvt.rna.tf32.f32 %0, %1;" : "=f"(y) : "f"(x)); return y;
}
__device__ __forceinline__ float ex2f(float x) {
    float y; asm("ex2.approx.ftz.f32 %0, %1;" : "=f"(y) : "f"(x)); return y;
}
__device__ __forceinline__ void mma8(float* c, const uint32_t* a, uint32_t b0, uint32_t b1) {
    asm volatile(
        "mma.sync.aligned.m16n8k8.row.col.f32.tf32.tf32.f32 "
        "{%0,%1,%2,%3}, {%4,%5,%6,%7}, {%8,%9}, {%0,%1,%2,%3};"
        : "+f"(c[0]), "+f"(c[1]), "+f"(c[2]), "+f"(c[3])
        : "r"(a[0]), "r"(a[1]), "r"(a[2]), "r"(a[3]), "r"(b0), "r"(b1));
}
__device__ __forceinline__ void ldsm4(uint32_t* r, uint32_t a) {
    asm volatile("ldmatrix.sync.aligned.m8n8.x4.shared.b16 {%0,%1,%2,%3}, [%4];"
        : "=r"(r[0]), "=r"(r[1]), "=r"(r[2]), "=r"(r[3]) : "r"(a));
}
#define CP16(dst, src) \
    asm volatile("cp.async.ca.shared.global [%0], [%1], 16;" :: "r"(dst), "l"(src))
#define CPCOMMIT() asm volatile("cp.async.commit_group;" ::: "memory")
#define CPWAIT0()  asm volatile("cp.async.wait_group 0;" ::: "memory")
#define STS64(addr, v0, v1) \
    asm volatile("st.shared.v2.f32 [%0], {%1, %2};" :: "r"(addr), "f"(v0), "f"(v1))

#define SWZ(row, col) ((uint32_t)(col) ^ ((uint32_t)((row) & 7) << 4))

// ============================================================================
// Fused weight transpose + tf32 round for ALL FOUR weights in one launch.
// z=0: Wq [512,256] -> wqt [256,512]   z=1: Wk likewise
// z=2: Wv [512,256] -> wvt [256,512]   z=3: Wo [256,512] -> wot [512,256]
// ============================================================================
__global__ void wprep_all(const float* __restrict__ Wq, const float* __restrict__ Wk,
                          const float* __restrict__ Wv, const float* __restrict__ Wo)
{
    __shared__ float ts[32][33];
    const int z = blockIdx.z;
    const float* W; float* WT; int K, N;
    if (z == 0)      { W = Wq; WT = g_wqt; K = DMODEL; N = KDIM; }
    else if (z == 1) { W = Wk; WT = g_wkt; K = DMODEL; N = KDIM; }
    else if (z == 2) { W = Wv; WT = g_wvt; K = DMODEL; N = VDIM; }
    else             { W = Wo; WT = g_wot; K = VDIM;  N = ODIM; }

    const int n0 = blockIdx.x * 32, k0 = blockIdx.y * 32;
    if (n0 >= N || k0 >= K) return;
    const int tx = threadIdx.x, ty = threadIdx.y;   // 32 x 8
    #pragma unroll
    for (int i = 0; i < 4; i++)
        ts[ty + i * 8][tx] = W[(size_t)(k0 + ty + i * 8) * N + n0 + tx];
    __syncthreads();
    #pragma unroll
    for (int i = 0; i < 4; i++)
        WT[(size_t)(n0 + ty + i * 8) * K + k0 + tx] = tf32r(ts[tx][ty + i * 8]);
}

// ============================================================================
// GEMM core (shared by fused-QKV and output projection).
// A[M,K] @ WT[N,K]^T + bias. BM=128, BN=64, BK=32; 8 warps 4(m)x2(n).
// mode 0: C[m][n]=tf32r((acc+b)*s)  mode 1: Ct[n][M]=tf32r((acc+b)*s)  mode 2: C=acc+b
// PRE_A: A already tf32-rounded -> stage via cp.async; else register round.
// ============================================================================
template<bool PRE_A>
__device__ __forceinline__ void gemm_body(
    const float* __restrict__ A, const float* __restrict__ WT,
    const float* __restrict__ bias, float* __restrict__ C,
    int M, int N, int K, float oscale, int mode,
    int m0, int n0, char* smg)
{
    const uint32_t sb = smem_u32(smg);
    const int tid = threadIdx.x;
    const int w = tid >> 5, lane = tid & 31;
    const int g = lane >> 2, t = lane & 3;
    const int wm = w >> 1, wn = w & 1;

    float acc[2][4][4];
    #pragma unroll
    for (int i = 0; i < 2; i++)
        #pragma unroll
        for (int j = 0; j < 4; j++)
            #pragma unroll
            for (int q = 0; q < 4; q++) acc[i][j][q] = 0.f;

    const int nkb = K >> 5;

    // prologue: stage block 0
    #pragma unroll
    for (int i = 0; i < 2; i++) {
        int idx = tid + i * 256;
        int n = idx >> 3, c = idx & 7;
        CP16(sb + 32768 + n * 128 + SWZ(n, c * 16), WT + (size_t)(n0 + n) * K + c * 4);
    }
    if (PRE_A) {
        #pragma unroll
        for (int i = 0; i < 4; i++) {
            int idx = tid + i * 256;
            int r = idx >> 3, c = idx & 7;
            CP16(sb + r * 128 + SWZ(r, c * 16), A + (size_t)(m0 + r) * K + c * 4);
        }
    } else {
        #pragma unroll
        for (int i = 0; i < 4; i++) {
            int idx = tid + i * 256;
            int r = idx >> 3, c = idx & 7;
            float4 v = *(const float4*)(A + (size_t)(m0 + r) * K + c * 4);
            v.x = tf32r(v.x); v.y = tf32r(v.y); v.z = tf32r(v.z); v.w = tf32r(v.w);
            *(float4*)(smg + r * 128 + SWZ(r, c * 16)) = v;
        }
    }
    CPCOMMIT(); CPWAIT0();
    __syncthreads();

    for (int kb = 0; kb < nkb; kb++) {
        const int cur = kb & 1;

        float4 pa[4];
        if (kb + 1 < nkb) {
            const uint32_t bd = sb + 32768 + (cur ^ 1) * 8192;
            #pragma unroll
            for (int i = 0; i < 2; i++) {
                int idx = tid + i * 256;
                int n = idx >> 3, c = idx & 7;
                CP16(bd + n * 128 + SWZ(n, c * 16),
                     WT + (size_t)(n0 + n) * K + (kb + 1) * 32 + c * 4);
            }
            if (PRE_A) {
                const uint32_t ad = sb + (cur ^ 1) * 16384;
                #pragma unroll
                for (int i = 0; i < 4; i++) {
                    int idx = tid + i * 256;
                    int r = idx >> 3, c = idx & 7;
                    CP16(ad + r * 128 + SWZ(r, c * 16),
                         A + (size_t)(m0 + r) * K + (kb + 1) * 32 + c * 4);
                }
            } else {
                #pragma unroll
                for (int i = 0; i < 4; i++) {
                    int idx = tid + i * 256;
                    int r = idx >> 3, c = idx & 7;
                    pa[i] = *(const float4*)(A + (size_t)(m0 + r) * K + (kb + 1) * 32 + c * 4);
                }
            }
            CPCOMMIT();
        }

        const uint32_t ab = sb + cur * 16384;
        const uint32_t bb = sb + 32768 + cur * 8192;
        #pragma unroll
        for (int kt = 0; kt < 4; kt++) {
            uint32_t af[2][4], bf[2][4];
            #pragma unroll
            for (int mt = 0; mt < 2; mt++) {
                int mr = wm * 32 + mt * 16 + (lane & 7) + ((lane >> 3) & 1) * 8;
                ldsm4(af[mt], ab + mr * 128 + SWZ(mr, kt * 32 + (lane >> 4) * 16));
            }
            #pragma unroll
            for (int p = 0; p < 2; p++) {
                int nr = wn * 32 + p * 16 + (lane & 7) + (lane >> 4) * 8;
                ldsm4(bf[p], bb + nr * 128 + SWZ(nr, kt * 32 + ((lane >> 3) & 1) * 16));
            }
            #pragma unroll
            for (int mt = 0; mt < 2; mt++)
                #pragma unroll
                for (int p = 0; p < 2; p++) {
                    mma8(acc[mt][2 * p],     af[mt], bf[p][0], bf[p][1]);
                    mma8(acc[mt][2 * p + 1], af[mt], bf[p][2], bf[p][3]);
                }
        }

        if (!PRE_A && kb + 1 < nkb) {
            char* ad = smg + (cur ^ 1) * 16384;
            #pragma unroll
            for (int i = 0; i < 4; i++) {
                int idx = tid + i * 256;
                int r = idx >> 3, c = idx & 7;
                float4 v = pa[i];
                v.x = tf32r(v.x); v.y = tf32r(v.y); v.z = tf32r(v.z); v.w = tf32r(v.w);
                *(float4*)(ad + r * 128 + SWZ(r, c * 16)) = v;
            }
        }
        CPWAIT0();
        __syncthreads();
    }

    // epilogue
    #pragma unroll
    for (int nt = 0; nt < 4; nt++) {
        int col = n0 + wn * 32 + nt * 8 + 2 * t;
        float2 bv = *(const float2*)(bias + col);
        #pragma unroll
        for (int mt = 0; mt < 2; mt++) {
            int row = m0 + wm * 32 + mt * 16 + g;
            float o0 = acc[mt][nt][0] + bv.x, o1 = acc[mt][nt][1] + bv.y;
            float o2 = acc[mt][nt][2] + bv.x, o3 = acc[mt][nt][3] + bv.y;
            if (mode == 0) {
                *(float2*)(C + (size_t)row * N + col) =
                    make_float2(tf32r(o0 * oscale), tf32r(o1 * oscale));
                *(float2*)(C + (size_t)(row + 8) * N + col) =
                    make_float2(tf32r(o2 * oscale), tf32r(o3 * oscale));
            } else if (mode == 1) {
                C[(size_t)col * M + row]           = tf32r(o0);
                C[(size_t)(col + 1) * M + row]     = tf32r(o1);
                C[(size_t)col * M + row + 8]       = tf32r(o2);
                C[(size_t)(col + 1) * M + row + 8] = tf32r(o3);
            } else {
                *(float2*)(C + (size_t)row * N + col) = make_float2(o0, o1);
                *(float2*)(C + (size_t)(row + 8) * N + col) = make_float2(o2, o3);
            }
        }
    }
}

// Fused QKV projections: blockIdx.z selects {Q,K,V}. M=4096, N=256, K=512.
__global__ __launch_bounds__(256) void gemm_qkv(
    const float* __restrict__ Q, const float* __restrict__ K_,
    const float* __restrict__ V,
    const float* __restrict__ bq, const float* __restrict__ bk,
    const float* __restrict__ bv)
{
    __shared__ char smg[49152];
    const int z = blockIdx.z;
    const float* A; const float* WT; const float* bias; float* C;
    float oscale; int mode;
    if (z == 0)      { A = Q;  WT = g_wqt; bias = bq; C = g_q;  oscale = LOG2E / 16.0f; mode = 0; }
    else if (z == 1) { A = K_; WT = g_wkt; bias = bk; C = g_k;  oscale = 1.0f;          mode = 0; }
    else             { A = V;  WT = g_wvt; bias = bv; C = g_vt; oscale = 1.0f;          mode = 1; }
    gemm_body<false>(A, WT, bias, C, MTOT, KDIM, DMODEL, oscale, mode,
                     blockIdx.y * 128, blockIdx.x * 64, smg);
}

// Output projection: M=4096, N=512, K=256; both operands pre-rounded.
__global__ __launch_bounds__(256) void gemm_out(
    const float* __restrict__ bo, float* __restrict__ out)
{
    __shared__ char smg[49152];
    gemm_body<true>(g_ctx, g_wot, bo, out, MTOT, ODIM, VDIM, 1.0f, 2,
                    blockIdx.y * 128, blockIdx.x * 64, smg);
}

// ============================================================================
// Flash attention (unchanged from R8). Smem 80KB.
// ============================================================================
#define ATTN_SMEM 81920

__global__ __launch_bounds__(256, 2) void attn_tc(
    const float* __restrict__ gq, const float* __restrict__ gk,
    const float* __restrict__ gvt, const float* __restrict__ mask,
    float* __restrict__ gctx)
{
    extern __shared__ char sma[];
    const uint32_t QB = smem_u32(sma);

    const int tid = threadIdx.x;
    const int w = tid >> 5, lane = tid & 31;
    const int g = lane >> 2, t = lane & 3;
    const int h = blockIdx.x, qt = blockIdx.y, b = blockIdx.z;

    const float* qsrc  = gq + ((size_t)(b * SEQ + qt * 128)) * KDIM + h * HDIM;
    const float* ksrc  = gk + ((size_t)(b * SEQ)) * KDIM + h * HDIM;
    const float* vtsrc = gvt + (size_t)(h * HDIM) * MTOT + b * SEQ;

    #pragma unroll
    for (int i = 0; i < 4; i++) {
        int idx = tid + i * 256;
        int r = idx >> 3, c = idx & 7;
        CP16(QB + r * 128 + SWZ(r, c * 16), qsrc + (size_t)r * KDIM + c * 4);
    }
    #pragma unroll
    for (int i = 0; i < 2; i++) {
        int idx = tid + i * 256;
        int r = idx >> 3, c = idx & 7;
        CP16(QB + 16384 + r * 128 + SWZ(r, c * 16), ksrc + (size_t)r * KDIM + c * 4);
    }
    #pragma unroll
    for (int i = 0; i < 2; i++) {
        int idx = tid + i * 256;
        int r = idx >> 4, c = idx & 15;
        CP16(QB + 32768 + r * 256 + SWZ(r, c * 16), vtsrc + (size_t)r * MTOT + c * 4);
    }
    CPCOMMIT(); CPWAIT0();
    __syncthreads();

    uint32_t qf[4][4];
    #pragma unroll
    for (int kt = 0; kt < 4; kt++) {
        int mr = w * 16 + (lane & 7) + ((lane >> 3) & 1) * 8;
        ldsm4(qf[kt], QB + mr * 128 + SWZ(mr, kt * 32 + (lane >> 4) * 16));
    }

    const float* mr0 = mask + (size_t)b * SEQ * SEQ
                     + (size_t)(qt * 128 + w * 16 + g) * SEQ + 2 * t;
    const float* mr1 = mr0 + (size_t)8 * SEQ;

    float ctx[4][4];
    #pragma unroll
    for (int i = 0; i < 4; i++)
        #pragma unroll
        for (int j = 0; j < 4; j++) ctx[i][j] = 0.f;
    float lg = 0.f, lh = 0.f;

    const uint32_t PB = QB + 49152 + w * 4096;
    const uint32_t ps0 = PB + g * 256;
    const uint32_t ps1 = PB + (g + 8) * 256;
    const uint32_t pr = (lane & 7) + ((lane >> 3) & 1) * 8;
    const uint32_t prow = PB + pr * 256;
    const uint32_t pcol0 = (lane >> 4) * 16;
    const uint32_t pswz = (pr & 7) << 4;

    for (int kt0 = 0; kt0 < 32; kt0++) {
        const int cur = kt0 & 1;

        if (kt0 < 31) {
            const uint32_t kd = QB + 16384 + (cur ^ 1) * 8192;
            const uint32_t vd = QB + 32768 + (cur ^ 1) * 8192;
            #pragma unroll
            for (int i = 0; i < 2; i++) {
                int idx = tid + i * 256;
                int r = idx >> 3, c = idx & 7;
                CP16(kd + r * 128 + SWZ(r, c * 16),
                     ksrc + (size_t)((kt0 + 1) * 64 + r) * KDIM + c * 4);
            }
            #pragma unroll
            for (int i = 0; i < 2; i++) {
                int idx = tid + i * 256;
                int r = idx >> 4, c = idx & 15;
                CP16(vd + r * 256 + SWZ(r, c * 16),
                     vtsrc + (size_t)r * MTOT + (kt0 + 1) * 64 + c * 4);
            }
            CPCOMMIT();
        }

        float2 m0v[8], m1v[8];
        #pragma unroll
        for (int nt = 0; nt < 8; nt++) {
            m0v[nt] = *(const float2*)(mr0 + kt0 * 64 + nt * 8);
            m1v[nt] = *(const float2*)(mr1 + kt0 * 64 + nt * 8);
        }

        float sc[8][4];
        #pragma unroll
        for (int nt = 0; nt < 8; nt++)
            #pragma unroll
            for (int i = 0; i < 4; i++) sc[nt][i] = 0.f;
        const uint32_t kbse = QB + 16384 + cur * 8192;
        #pragma unroll
        for (int kt = 0; kt < 4; kt++) {
            #pragma unroll
            for (int p = 0; p < 4; p++) {
                int kr = p * 16 + (lane & 7) + (lane >> 4) * 8;
                uint32_t bf[4];
                ldsm4(bf, kbse + kr * 128 + SWZ(kr, kt * 32 + ((lane >> 3) & 1) * 16));
                mma8(sc[2 * p],     qf[kt], bf[0], bf[1]);
                mma8(sc[2 * p + 1], qf[kt], bf[2], bf[3]);
            }
        }

        #pragma unroll
        for (int nt = 0; nt < 8; nt++) {
            float p0 = ex2f(__fmaf_rn(m0v[nt].x, LOG2E, sc[nt][0]));
            float p1 = ex2f(__fmaf_rn(m0v[nt].y, LOG2E, sc[nt][1]));
            float p2 = ex2f(__fmaf_rn(m1v[nt].x, LOG2E, sc[nt][2]));
            float p3 = ex2f(__fmaf_rn(m1v[nt].y, LOG2E, sc[nt][3]));
            lg += p0 + p1;
            lh += p2 + p3;
            uint32_t cb = (uint32_t)(nt * 32 + t * 8);
            STS64(ps0 + (cb ^ ((g & 7) << 4)),       tf32r(p0), tf32r(p1));
            STS64(ps1 + (cb ^ (((g + 8) & 7) << 4)), tf32r(p2), tf32r(p3));
        }
        __syncwarp();

        const uint32_t vbse = QB + 32768 + cur * 8192;
        #pragma unroll
        for (int kc = 0; kc < 8; kc++) {
            uint32_t a[4];
            ldsm4(a, prow + (((uint32_t)(kc * 32) + pcol0) ^ pswz));
            #pragma unroll
            for (int p = 0; p < 2; p++) {
                int dr = p * 16 + (lane & 7) + (lane >> 4) * 8;
                uint32_t bf[4];
                ldsm4(bf, vbse + dr * 256 + SWZ(dr, kc * 32 + ((lane >> 3) & 1) * 16));
                mma8(ctx[2 * p],     a, bf[0], bf[1]);
                mma8(ctx[2 * p + 1], a, bf[2], bf[3]);
            }
        }

        if (kt0 < 31) CPWAIT0();
        __syncthreads();
    }

    lg += __shfl_xor_sync(0xFFFFFFFFu, lg, 1);
    lg += __shfl_xor_sync(0xFFFFFFFFu, lg, 2);
    lh += __shfl_xor_sync(0xFFFFFFFFu, lh, 1);
    lh += __shfl_xor_sync(0xFFFFFFFFu, lh, 2);
    float ig = 1.0f / lg, ih = 1.0f / lh;

    size_t rbase = ((size_t)(b * SEQ + qt * 128 + w * 16 + g)) * VDIM + h * HDIM;
    #pragma unroll
    for (int nt = 0; nt < 4; nt++) {
        int col = nt * 8 + 2 * t;
        *(float2*)(gctx + rbase + col) =
            make_float2(tf32r(ctx[nt][0] * ig), tf32r(ctx[nt][1] * ig));
        *(float2*)(gctx + rbase + (size_t)8 * VDIM + col) =
            make_float2(tf32r(ctx[nt][2] * ih), tf32r(ctx[nt][3] * ih));
    }
}

// ---------------- launch ----------------
extern "C" void kernel_launch(void* const* d_in, const int* in_sizes, int n_in,
                              void* d_out, int out_size)
{
    const float* V    = (const float*)d_in[0];
    const float* Q    = (const float*)d_in[1];
    const float* K    = (const float*)d_in[2];
    const float* mask = (const float*)d_in[3];
    const float* Wq   = (const float*)d_in[4];
    const float* bq   = (const float*)d_in[5];
    const float* Wk   = (const float*)d_in[6];
    const float* bk   = (const float*)d_in[7];
    const float* Wv   = (const float*)d_in[8];
    const float* bv   = (const float*)d_in[9];
    const float* Wo   = (const float*)d_in[10];
    const float* bo   = (const float*)d_in[11];
    float* out = (float*)d_out;

    float *dq, *dk, *dvt, *dctx;
    cudaGetSymbolAddress((void**)&dq,   g_q);
    cudaGetSymbolAddress((void**)&dk,   g_k);
    cudaGetSymbolAddress((void**)&dvt,  g_vt);
    cudaGetSymbolAddress((void**)&dctx, g_ctx);

    // 1) all weight transposes in one launch (max dims: N=512 -> x=16, K=512 -> y=16)
    wprep_all<<<dim3(16, 16, 4), dim3(32, 8)>>>(Wq, Wk, Wv, Wo);

    // 2) fused QKV projections: one launch, z selects matrix
    gemm_qkv<<<dim3(KDIM / 64, MTOT / 128, 3), 256>>>(Q, K, V, bq, bk, bv);

    // 3) attention
    cudaFuncSetAttribute(attn_tc, cudaFuncAttributeMaxDynamicSharedMemorySize, ATTN_SMEM);
    attn_tc<<<dim3(NHEADS, SEQ / 128, BATCH), 256, ATTN_SMEM>>>(dq, dk, dvt, mask, dctx);

    // 4) output projection
    gemm_out<<<dim3(ODIM / 64, MTOT / 128), 256>>>(bo, out);
}

// round 10
// speedup vs baseline: 3.7893x; 1.0664x over previous
#include <cuda_runtime.h>
#include <cstdint>

// ---------------- problem constants ----------------
#define BATCH 2
#define SEQ 2048
#define DMODEL 512
#define KDIM 256
#define VDIM 256
#define ODIM 512
#define NHEADS 8
#define HDIM 32
#define LOG2E 1.4426950408889634f
#define MTOT (BATCH * SEQ)          // 4096

// scratch
__device__ float g_q[MTOT * KDIM];
__device__ float g_k[MTOT * KDIM];
__device__ float g_vt[KDIM * MTOT];    // V projection, transposed: [n=256][m=4096]
__device__ float g_ctx[MTOT * VDIM];   // tf32-rounded context
__device__ float g_wqt[KDIM * DMODEL]; // Wq^T [256][512], tf32-rounded
__device__ float g_wkt[KDIM * DMODEL];
__device__ float g_wvt[VDIM * DMODEL];
__device__ float g_wot[ODIM * VDIM];   // Wo^T [512][256]

// ---------------- helpers ----------------
__device__ __forceinline__ uint32_t smem_u32(const void* p) {
    uint32_t a;
    asm("{ .reg .u64 t; cvta.to.shared.u64 t, %1; cvt.u32.u64 %0, t; }" : "=r"(a) : "l"(p));
    return a;
}
__device__ __forceinline__ float tf32r(float x) {
    float y; asm("cvt.rna.tf32.f32 %0, %1;" : "=f"(y) : "f"(x)); return y;
}
__device__ __forceinline__ float ex2f(float x) {
    float y; asm("ex2.approx.ftz.f32 %0, %1;" : "=f"(y) : "f"(x)); return y;
}
__device__ __forceinline__ void mma8(float* c, const uint32_t* a, uint32_t b0, uint32_t b1) {
    asm volatile(
        "mma.sync.aligned.m16n8k8.row.col.f32.tf32.tf32.f32 "
        "{%0,%1,%2,%3}, {%4,%5,%6,%7}, {%8,%9}, {%0,%1,%2,%3};"
        : "+f"(c[0]), "+f"(c[1]), "+f"(c[2]), "+f"(c[3])
        : "r"(a[0]), "r"(a[1]), "r"(a[2]), "r"(a[3]), "r"(b0), "r"(b1));
}
__device__ __forceinline__ void ldsm4(uint32_t* r, uint32_t a) {
    asm volatile("ldmatrix.sync.aligned.m8n8.x4.shared.b16 {%0,%1,%2,%3}, [%4];"
        : "=r"(r[0]), "=r"(r[1]), "=r"(r[2]), "=r"(r[3]) : "r"(a));
}
#define CP16(dst, src) \
    asm volatile("cp.async.ca.shared.global [%0], [%1], 16;" :: "r"(dst), "l"(src))
#define CPCOMMIT() asm volatile("cp.async.commit_group;" ::: "memory")
#define CPWAIT0()  asm volatile("cp.async.wait_group 0;" ::: "memory")
#define STS64(addr, v0, v1) \
    asm volatile("st.shared.v2.f32 [%0], {%1, %2};" :: "r"(addr), "f"(v0), "f"(v1))

#define SWZ(row, col) ((uint32_t)(col) ^ ((uint32_t)((row) & 7) << 4))

// ============================================================================
// Fused weight transpose + tf32 round for all four weights (one launch).
// ============================================================================
__global__ void wprep_all(const float* __restrict__ Wq, const float* __restrict__ Wk,
                          const float* __restrict__ Wv, const float* __restrict__ Wo)
{
    __shared__ float ts[32][33];
    const int z = blockIdx.z;
    const float* W; float* WT; int K, N;
    if (z == 0)      { W = Wq; WT = g_wqt; K = DMODEL; N = KDIM; }
    else if (z == 1) { W = Wk; WT = g_wkt; K = DMODEL; N = KDIM; }
    else if (z == 2) { W = Wv; WT = g_wvt; K = DMODEL; N = VDIM; }
    else             { W = Wo; WT = g_wot; K = VDIM;  N = ODIM; }

    const int n0 = blockIdx.x * 32, k0 = blockIdx.y * 32;
    if (n0 >= N || k0 >= K) return;
    const int tx = threadIdx.x, ty = threadIdx.y;   // 32 x 8
    #pragma unroll
    for (int i = 0; i < 4; i++)
        ts[ty + i * 8][tx] = W[(size_t)(k0 + ty + i * 8) * N + n0 + tx];
    __syncthreads();
    #pragma unroll
    for (int i = 0; i < 4; i++)
        WT[(size_t)(n0 + ty + i * 8) * K + k0 + tx] = tf32r(ts[tx][ty + i * 8]);
}

// ============================================================================
// GEMM core. A[M,K] @ WT[N,K]^T + bias. BM=128, BN=64, BK=32; 8 warps.
// ============================================================================
template<bool PRE_A>
__device__ __forceinline__ void gemm_body(
    const float* __restrict__ A, const float* __restrict__ WT,
    const float* __restrict__ bias, float* __restrict__ C,
    int M, int N, int K, float oscale, int mode,
    int m0, int n0, char* smg)
{
    const uint32_t sb = smem_u32(smg);
    const int tid = threadIdx.x;
    const int w = tid >> 5, lane = tid & 31;
    const int g = lane >> 2, t = lane & 3;
    const int wm = w >> 1, wn = w & 1;

    float acc[2][4][4];
    #pragma unroll
    for (int i = 0; i < 2; i++)
        #pragma unroll
        for (int j = 0; j < 4; j++)
            #pragma unroll
            for (int q = 0; q < 4; q++) acc[i][j][q] = 0.f;

    const int nkb = K >> 5;

    #pragma unroll
    for (int i = 0; i < 2; i++) {
        int idx = tid + i * 256;
        int n = idx >> 3, c = idx & 7;
        CP16(sb + 32768 + n * 128 + SWZ(n, c * 16), WT + (size_t)(n0 + n) * K + c * 4);
    }
    if (PRE_A) {
        #pragma unroll
        for (int i = 0; i < 4; i++) {
            int idx = tid + i * 256;
            int r = idx >> 3, c = idx & 7;
            CP16(sb + r * 128 + SWZ(r, c * 16), A + (size_t)(m0 + r) * K + c * 4);
        }
    } else {
        #pragma unroll
        for (int i = 0; i < 4; i++) {
            int idx = tid + i * 256;
            int r = idx >> 3, c = idx & 7;
            float4 v = *(const float4*)(A + (size_t)(m0 + r) * K + c * 4);
            v.x = tf32r(v.x); v.y = tf32r(v.y); v.z = tf32r(v.z); v.w = tf32r(v.w);
            *(float4*)(smg + r * 128 + SWZ(r, c * 16)) = v;
        }
    }
    CPCOMMIT(); CPWAIT0();
    __syncthreads();

    for (int kb = 0; kb < nkb; kb++) {
        const int cur = kb & 1;

        float4 pa[4];
        if (kb + 1 < nkb) {
            const uint32_t bd = sb + 32768 + (cur ^ 1) * 8192;
            #pragma unroll
            for (int i = 0; i < 2; i++) {
                int idx = tid + i * 256;
                int n = idx >> 3, c = idx & 7;
                CP16(bd + n * 128 + SWZ(n, c * 16),
                     WT + (size_t)(n0 + n) * K + (kb + 1) * 32 + c * 4);
            }
            if (PRE_A) {
                const uint32_t ad = sb + (cur ^ 1) * 16384;
                #pragma unroll
                for (int i = 0; i < 4; i++) {
                    int idx = tid + i * 256;
                    int r = idx >> 3, c = idx & 7;
                    CP16(ad + r * 128 + SWZ(r, c * 16),
                         A + (size_t)(m0 + r) * K + (kb + 1) * 32 + c * 4);
                }
            } else {
                #pragma unroll
                for (int i = 0; i < 4; i++) {
                    int idx = tid + i * 256;
                    int r = idx >> 3, c = idx & 7;
                    pa[i] = *(const float4*)(A + (size_t)(m0 + r) * K + (kb + 1) * 32 + c * 4);
                }
            }
            CPCOMMIT();
        }

        const uint32_t ab = sb + cur * 16384;
        const uint32_t bb = sb + 32768 + cur * 8192;
        #pragma unroll
        for (int kt = 0; kt < 4; kt++) {
            uint32_t af[2][4], bf[2][4];
            #pragma unroll
            for (int mt = 0; mt < 2; mt++) {
                int mr = wm * 32 + mt * 16 + (lane & 7) + ((lane >> 3) & 1) * 8;
                ldsm4(af[mt], ab + mr * 128 + SWZ(mr, kt * 32 + (lane >> 4) * 16));
            }
            #pragma unroll
            for (int p = 0; p < 2; p++) {
                int nr = wn * 32 + p * 16 + (lane & 7) + (lane >> 4) * 8;
                ldsm4(bf[p], bb + nr * 128 + SWZ(nr, kt * 32 + ((lane >> 3) & 1) * 16));
            }
            #pragma unroll
            for (int mt = 0; mt < 2; mt++)
                #pragma unroll
                for (int p = 0; p < 2; p++) {
                    mma8(acc[mt][2 * p],     af[mt], bf[p][0], bf[p][1]);
                    mma8(acc[mt][2 * p + 1], af[mt], bf[p][2], bf[p][3]);
                }
        }

        if (!PRE_A && kb + 1 < nkb) {
            char* ad = smg + (cur ^ 1) * 16384;
            #pragma unroll
            for (int i = 0; i < 4; i++) {
                int idx = tid + i * 256;
                int r = idx >> 3, c = idx & 7;
                float4 v = pa[i];
                v.x = tf32r(v.x); v.y = tf32r(v.y); v.z = tf32r(v.z); v.w = tf32r(v.w);
                *(float4*)(ad + r * 128 + SWZ(r, c * 16)) = v;
            }
        }
        CPWAIT0();
        __syncthreads();
    }

    #pragma unroll
    for (int nt = 0; nt < 4; nt++) {
        int col = n0 + wn * 32 + nt * 8 + 2 * t;
        float2 bv = *(const float2*)(bias + col);
        #pragma unroll
        for (int mt = 0; mt < 2; mt++) {
            int row = m0 + wm * 32 + mt * 16 + g;
            float o0 = acc[mt][nt][0] + bv.x, o1 = acc[mt][nt][1] + bv.y;
            float o2 = acc[mt][nt][2] + bv.x, o3 = acc[mt][nt][3] + bv.y;
            if (mode == 0) {
                *(float2*)(C + (size_t)row * N + col) =
                    make_float2(tf32r(o0 * oscale), tf32r(o1 * oscale));
                *(float2*)(C + (size_t)(row + 8) * N + col) =
                    make_float2(tf32r(o2 * oscale), tf32r(o3 * oscale));
            } else if (mode == 1) {
                C[(size_t)col * M + row]           = tf32r(o0);
                C[(size_t)(col + 1) * M + row]     = tf32r(o1);
                C[(size_t)col * M + row + 8]       = tf32r(o2);
                C[(size_t)(col + 1) * M + row + 8] = tf32r(o3);
            } else {
                *(float2*)(C + (size_t)row * N + col) = make_float2(o0, o1);
                *(float2*)(C + (size_t)(row + 8) * N + col) = make_float2(o2, o3);
            }
        }
    }
}

__global__ __launch_bounds__(256) void gemm_qkv(
    const float* __restrict__ Q, const float* __restrict__ K_,
    const float* __restrict__ V,
    const float* __restrict__ bq, const float* __restrict__ bk,
    const float* __restrict__ bv)
{
    __shared__ char smg[49152];
    const int z = blockIdx.z;
    const float* A; const float* WT; const float* bias; float* C;
    float oscale; int mode;
    if (z == 0)      { A = Q;  WT = g_wqt; bias = bq; C = g_q;  oscale = LOG2E / 16.0f; mode = 0; }
    else if (z == 1) { A = K_; WT = g_wkt; bias = bk; C = g_k;  oscale = 1.0f;          mode = 0; }
    else             { A = V;  WT = g_wvt; bias = bv; C = g_vt; oscale = 1.0f;          mode = 1; }
    gemm_body<false>(A, WT, bias, C, MTOT, KDIM, DMODEL, oscale, mode,
                     blockIdx.y * 128, blockIdx.x * 64, smg);
}

__global__ __launch_bounds__(256) void gemm_out(
    const float* __restrict__ bo, float* __restrict__ out)
{
    __shared__ char smg[49152];
    gemm_body<true>(g_ctx, g_wot, bo, out, MTOT, ODIM, VDIM, 1.0f, 2,
                    blockIdx.y * 128, blockIdx.x * 64, smg);
}

// ============================================================================
// Flash attention: 4 warps/CTA, each warp owns 32 q-rows (two m16 blocks).
// Halves K/V ldsm redundancy vs 8-warp/16-row layout.
// Smem: Q 16KB @0 | K 2x8KB @16384 | Vt 2x8KB @32768 | P 4x8KB @49152 = 80KB.
// ============================================================================
#define ATTN_SMEM 81920

__global__ __launch_bounds__(128, 2) void attn_tc(
    const float* __restrict__ gq, const float* __restrict__ gk,
    const float* __restrict__ gvt, const float* __restrict__ mask,
    float* __restrict__ gctx)
{
    extern __shared__ char sma[];
    const uint32_t QB = smem_u32(sma);

    const int tid = threadIdx.x;
    const int w = tid >> 5, lane = tid & 31;
    const int g = lane >> 2, t = lane & 3;
    const int h = blockIdx.x, qt = blockIdx.y, b = blockIdx.z;

    const float* qsrc  = gq + ((size_t)(b * SEQ + qt * 128)) * KDIM + h * HDIM;
    const float* ksrc  = gk + ((size_t)(b * SEQ)) * KDIM + h * HDIM;
    const float* vtsrc = gvt + (size_t)(h * HDIM) * MTOT + b * SEQ;

    // prologue: Q (16KB) + K0 + V0 via cp.async; 128 threads
    #pragma unroll
    for (int i = 0; i < 8; i++) {
        int idx = tid + i * 128;
        int r = idx >> 3, c = idx & 7;
        CP16(QB + r * 128 + SWZ(r, c * 16), qsrc + (size_t)r * KDIM + c * 4);
    }
    #pragma unroll
    for (int i = 0; i < 4; i++) {
        int idx = tid + i * 128;
        int r = idx >> 3, c = idx & 7;
        CP16(QB + 16384 + r * 128 + SWZ(r, c * 16), ksrc + (size_t)r * KDIM + c * 4);
    }
    #pragma unroll
    for (int i = 0; i < 4; i++) {
        int idx = tid + i * 128;
        int r = idx >> 4, c = idx & 15;
        CP16(QB + 32768 + r * 256 + SWZ(r, c * 16), vtsrc + (size_t)r * MTOT + c * 4);
    }
    CPCOMMIT(); CPWAIT0();
    __syncthreads();

    // Q fragments: 2 m-blocks x 4 k-tiles (held for whole kernel)
    uint32_t qf[2][4][4];
    #pragma unroll
    for (int mb = 0; mb < 2; mb++)
        #pragma unroll
        for (int kt = 0; kt < 4; kt++) {
            int mr = w * 32 + mb * 16 + (lane & 7) + ((lane >> 3) & 1) * 8;
            ldsm4(qf[mb][kt], QB + mr * 128 + SWZ(mr, kt * 32 + (lane >> 4) * 16));
        }

    // mask row pointers: rows (w*32 + mb*16 + g) and +8
    const float* mrow[2][2];
    #pragma unroll
    for (int mb = 0; mb < 2; mb++) {
        mrow[mb][0] = mask + (size_t)b * SEQ * SEQ
                    + (size_t)(qt * 128 + w * 32 + mb * 16 + g) * SEQ + 2 * t;
        mrow[mb][1] = mrow[mb][0] + (size_t)8 * SEQ;
    }

    float ctx[2][4][4];
    #pragma unroll
    for (int mb = 0; mb < 2; mb++)
        #pragma unroll
        for (int i = 0; i < 4; i++)
            #pragma unroll
            for (int j = 0; j < 4; j++) ctx[mb][i][j] = 0.f;
    float lsum[2][2] = {{0.f, 0.f}, {0.f, 0.f}};

    const uint32_t PB = QB + 49152 + w * 8192;   // per-warp P: 32 rows x 256B
    const uint32_t pr = (lane & 7) + ((lane >> 3) & 1) * 8;
    const uint32_t pcol0 = (lane >> 4) * 16;
    const uint32_t pswz = (pr & 7) << 4;
    const uint32_t stswz = (uint32_t)(g & 7) << 4;   // (g+8)&7 == g&7

    for (int kt0 = 0; kt0 < 32; kt0++) {
        const int cur = kt0 & 1;

        if (kt0 < 31) {
            const uint32_t kd = QB + 16384 + (cur ^ 1) * 8192;
            const uint32_t vd = QB + 32768 + (cur ^ 1) * 8192;
            #pragma unroll
            for (int i = 0; i < 4; i++) {
                int idx = tid + i * 128;
                int r = idx >> 3, c = idx & 7;
                CP16(kd + r * 128 + SWZ(r, c * 16),
                     ksrc + (size_t)((kt0 + 1) * 64 + r) * KDIM + c * 4);
            }
            #pragma unroll
            for (int i = 0; i < 4; i++) {
                int idx = tid + i * 128;
                int r = idx >> 4, c = idx & 15;
                CP16(vd + r * 256 + SWZ(r, c * 16),
                     vtsrc + (size_t)r * MTOT + (kt0 + 1) * 64 + c * 4);
            }
            CPCOMMIT();
        }

        const uint32_t kbse = QB + 16384 + cur * 8192;

        // S + exp in two 32-key halves (keeps sc at 32 regs)
        #pragma unroll
        for (int nh = 0; nh < 2; nh++) {
            // mask prefetch for this half: [mb][rowhalf][nb]
            float2 mv[2][2][4];
            #pragma unroll
            for (int mb = 0; mb < 2; mb++)
                #pragma unroll
                for (int rh = 0; rh < 2; rh++)
                    #pragma unroll
                    for (int nb = 0; nb < 4; nb++)
                        mv[mb][rh][nb] = *(const float2*)(mrow[mb][rh] + kt0 * 64 + nh * 32 + nb * 8);

            float sc[2][4][4];
            #pragma unroll
            for (int mb = 0; mb < 2; mb++)
                #pragma unroll
                for (int i = 0; i < 4; i++)
                    #pragma unroll
                    for (int j = 0; j < 4; j++) sc[mb][i][j] = 0.f;

            #pragma unroll
            for (int kt = 0; kt < 4; kt++) {
                #pragma unroll
                for (int p = 0; p < 2; p++) {
                    int kr = nh * 32 + p * 16 + (lane & 7) + (lane >> 4) * 8;
                    uint32_t bf[4];
                    ldsm4(bf, kbse + kr * 128 + SWZ(kr, kt * 32 + ((lane >> 3) & 1) * 16));
                    #pragma unroll
                    for (int mb = 0; mb < 2; mb++) {
                        mma8(sc[mb][2 * p],     qf[mb][kt], bf[0], bf[1]);
                        mma8(sc[mb][2 * p + 1], qf[mb][kt], bf[2], bf[3]);
                    }
                }
            }

            // exp + P store
            #pragma unroll
            for (int mb = 0; mb < 2; mb++) {
                const uint32_t ps0 = PB + (uint32_t)(mb * 16 + g) * 256;
                const uint32_t ps1 = PB + (uint32_t)(mb * 16 + g + 8) * 256;
                #pragma unroll
                for (int nb = 0; nb < 4; nb++) {
                    float p0 = ex2f(__fmaf_rn(mv[mb][0][nb].x, LOG2E, sc[mb][nb][0]));
                    float p1 = ex2f(__fmaf_rn(mv[mb][0][nb].y, LOG2E, sc[mb][nb][1]));
                    float p2 = ex2f(__fmaf_rn(mv[mb][1][nb].x, LOG2E, sc[mb][nb][2]));
                    float p3 = ex2f(__fmaf_rn(mv[mb][1][nb].y, LOG2E, sc[mb][nb][3]));
                    lsum[mb][0] += p0 + p1;
                    lsum[mb][1] += p2 + p3;
                    uint32_t cb = (uint32_t)(nh * 128 + nb * 32 + t * 8);
                    STS64(ps0 + (cb ^ stswz), tf32r(p0), tf32r(p1));
                    STS64(ps1 + (cb ^ stswz), tf32r(p2), tf32r(p3));
                }
            }
        }
        __syncwarp();

        // ctx += P @ V over all 64 keys
        const uint32_t vbse = QB + 32768 + cur * 8192;
        #pragma unroll
        for (int kc = 0; kc < 8; kc++) {
            uint32_t a[2][4];
            #pragma unroll
            for (int mb = 0; mb < 2; mb++)
                ldsm4(a[mb], PB + (uint32_t)(mb * 16 + pr) * 256
                           + (((uint32_t)(kc * 32) + pcol0) ^ pswz));
            #pragma unroll
            for (int p = 0; p < 2; p++) {
                int dr = p * 16 + (lane & 7) + (lane >> 4) * 8;
                uint32_t bf[4];
                ldsm4(bf, vbse + dr * 256 + SWZ(dr, kc * 32 + ((lane >> 3) & 1) * 16));
                #pragma unroll
                for (int mb = 0; mb < 2; mb++) {
                    mma8(ctx[mb][2 * p],     a[mb], bf[0], bf[1]);
                    mma8(ctx[mb][2 * p + 1], a[mb], bf[2], bf[3]);
                }
            }
        }

        if (kt0 < 31) CPWAIT0();
        __syncthreads();
    }

    // reduce row sums across the 4 lanes of each group
    #pragma unroll
    for (int mb = 0; mb < 2; mb++)
        #pragma unroll
        for (int rh = 0; rh < 2; rh++) {
            float v = lsum[mb][rh];
            v += __shfl_xor_sync(0xFFFFFFFFu, v, 1);
            v += __shfl_xor_sync(0xFFFFFFFFu, v, 2);
            lsum[mb][rh] = 1.0f / v;
        }

    #pragma unroll
    for (int mb = 0; mb < 2; mb++) {
        size_t rbase = ((size_t)(b * SEQ + qt * 128 + w * 32 + mb * 16 + g)) * VDIM + h * HDIM;
        float ig = lsum[mb][0], ih = lsum[mb][1];
        #pragma unroll
        for (int nt = 0; nt < 4; nt++) {
            int col = nt * 8 + 2 * t;
            *(float2*)(gctx + rbase + col) =
                make_float2(tf32r(ctx[mb][nt][0] * ig), tf32r(ctx[mb][nt][1] * ig));
            *(float2*)(gctx + rbase + (size_t)8 * VDIM + col) =
                make_float2(tf32r(ctx[mb][nt][2] * ih), tf32r(ctx[mb][nt][3] * ih));
        }
    }
}

// ---------------- launch ----------------
extern "C" void kernel_launch(void* const* d_in, const int* in_sizes, int n_in,
                              void* d_out, int out_size)
{
    const float* V    = (const float*)d_in[0];
    const float* Q    = (const float*)d_in[1];
    const float* K    = (const float*)d_in[2];
    const float* mask = (const float*)d_in[3];
    const float* bq   = (const float*)d_in[5];
    const float* bk   = (const float*)d_in[7];
    const float* bv   = (const float*)d_in[9];
    const float* bo   = (const float*)d_in[11];
    const float* Wq   = (const float*)d_in[4];
    const float* Wk   = (const float*)d_in[6];
    const float* Wv   = (const float*)d_in[8];
    const float* Wo   = (const float*)d_in[10];
    float* out = (float*)d_out;

    float *dq, *dk, *dvt, *dctx;
    cudaGetSymbolAddress((void**)&dq,   g_q);
    cudaGetSymbolAddress((void**)&dk,   g_k);
    cudaGetSymbolAddress((void**)&dvt,  g_vt);
    cudaGetSymbolAddress((void**)&dctx, g_ctx);

    // 1) all weight transposes in one launch
    wprep_all<<<dim3(16, 16, 4), dim3(32, 8)>>>(Wq, Wk, Wv, Wo);

    // 2) fused QKV projections
    gemm_qkv<<<dim3(KDIM / 64, MTOT / 128, 3), 256>>>(Q, K, V, bq, bk, bv);

    // 3) attention (128 threads, 4 warps, 32 q-rows/warp)
    cudaFuncSetAttribute(attn_tc, cudaFuncAttributeMaxDynamicSharedMemorySize, ATTN_SMEM);
    attn_tc<<<dim3(NHEADS, SEQ / 128, BATCH), 128, ATTN_SMEM>>>(dq, dk, dvt, mask, dctx);

    // 4) output projection
    gemm_out<<<dim3(ODIM / 64, MTOT / 128), 256>>>(bo, out);
}